// round 12
// baseline (speedup 1.0000x reference)
#include <cuda_runtime.h>
#include <cuda_bf16.h>
#include <cstdint>
#include <cstddef>

// Problem constants
#define DD   128
#define NB   4
#define NSRC 10000
#define NTGT 10000
#define NE   160000
#define NK   16

// Scratch (device globals: allocation-free rule)
__device__ float g_sproj [NB * NSRC * DD];
__device__ float g_tproj [NB * NTGT * DD];
__device__ float g_tproj2[NB * NTGT * DD];
__device__ float g_dbond [NB * NE * DD];

typedef unsigned long long u64;
typedef unsigned int       u32;

// ==================== mma.sync (HMMA) GEMM machinery =========================
// Tile: 128 rows x 128 cols x K=128 per CTA. bf16 hi/lo split, 3 passes.
// All instructions are baseline PTX (sm_80+): compiles for sm_103.

#define TM 128
#define AH_STRIDE 136                    // bf16 elems per row (272B, conflict-free ldmatrix)
#define ROWB      (AH_STRIDE * 2)        // 272 bytes per tile row

// smem byte offsets
#define SM_AH   0                        // A hi  [128][136] bf16 = 34816 B
#define SM_AL   34816                    // A lo
#define SM_WH   69632                    // W^T hi [n][k] bf16
#define SM_WL   104448                   // W^T lo
#define SM_STG  139264                   // W fp32 staging (stride 129) then D staging (stride 132)
#define SM_TOTAL 206848
#define WSTG_STRIDE 129
#define DST_STRIDE  132

static __device__ __forceinline__ u32 smem_u32(const void* p) {
    u32 a;
    asm("{ .reg .u64 t; cvta.to.shared.u64 t, %1; cvt.u32.u64 %0, t; }" : "=r"(a) : "l"(p));
    return a;
}

static __device__ __forceinline__ void ldmatrix_x4(u32* r, u32 addr) {
    asm volatile("ldmatrix.sync.aligned.m8n8.x4.shared.b16 {%0,%1,%2,%3}, [%4];"
                 : "=r"(r[0]), "=r"(r[1]), "=r"(r[2]), "=r"(r[3]) : "r"(addr));
}

static __device__ __forceinline__ void mma_bf16(float* c, const u32* a, u32 b0, u32 b1) {
    asm volatile("mma.sync.aligned.m16n8k16.row.col.f32.bf16.bf16.f32 "
                 "{%0,%1,%2,%3}, {%4,%5,%6,%7}, {%8,%9}, {%0,%1,%2,%3};"
                 : "+f"(c[0]), "+f"(c[1]), "+f"(c[2]), "+f"(c[3])
                 : "r"(a[0]), "r"(a[1]), "r"(a[2]), "r"(a[3]), "r"(b0), "r"(b1));
}

static __device__ __forceinline__ void split_bf16(float x, unsigned short& h, unsigned short& l) {
    __nv_bfloat16 hb = __float2bfloat16_rn(x);
    float xh = __bfloat162float(hb);
    __nv_bfloat16 lb = __float2bfloat16_rn(x - xh);
    h = __bfloat16_as_ushort(hb);
    l = __bfloat16_as_ushort(lb);
}

static __device__ __forceinline__ float silu_f(float x) {
    return x / (1.0f + __expf(-x));
}

static __device__ __forceinline__ void warp_ln_stats(float z0, float z1, float z2, float z3,
                                                     float& mean, float& rstd) {
    float s  = z0 + z1 + z2 + z3;
    float s2 = z0 * z0 + z1 * z1 + z2 * z2 + z3 * z3;
#pragma unroll
    for (int off = 16; off; off >>= 1) {
        s  += __shfl_xor_sync(0xffffffffu, s,  off);
        s2 += __shfl_xor_sync(0xffffffffu, s2, off);
    }
    mean = s * (1.0f / DD);
    float var = s2 * (1.0f / DD) - mean * mean;
    rstd = rsqrtf(var + 1e-5f);
}

// --- prologue: X -> A hi/lo tiles; W -> W^T hi/lo tiles ----------------------
static __device__ __forceinline__ void mma_prologue(char* sm,
                                                    const float* __restrict__ Xrow0, int rowsValid,
                                                    const float* __restrict__ W,
                                                    int tid, int warp, int lane) {
    // A load + split: 128 rows x 32 float4 = 4096 float4 (clamp rows for partial tiles)
    {
        const float4* Xf4 = (const float4*)Xrow0;
#pragma unroll
        for (int i = 0; i < 16; ++i) {
            int f = tid + i * 256;           // 4096 float4
            int r = f >> 5, c4 = (f & 31) << 2;
            int rr = (r < rowsValid) ? r : (rowsValid - 1);
            float4 v = Xf4[rr * 32 + (f & 31)];
            unsigned short h0, l0, h1, l1, h2, l2, h3, l3;
            split_bf16(v.x, h0, l0); split_bf16(v.y, h1, l1);
            split_bf16(v.z, h2, l2); split_bf16(v.w, h3, l3);
            u64 hp = (u64)h0 | ((u64)h1 << 16) | ((u64)h2 << 32) | ((u64)h3 << 48);
            u64 lp = (u64)l0 | ((u64)l1 << 16) | ((u64)l2 << 32) | ((u64)l3 << 48);
            u32 off = (u32)((r * AH_STRIDE + c4) * 2);
            *(u64*)(sm + SM_AH + off) = hp;
            *(u64*)(sm + SM_AL + off) = lp;
        }
    }
    // W fp32 staging (coalesced gmem reads)
    {
        float* Wstg = (float*)(sm + SM_STG);
        const float4* Wf4 = (const float4*)W;
#pragma unroll
        for (int i = 0; i < 16; ++i) {
            int f = tid + i * 256;           // 4096 float4
            int k = f >> 5, n4 = (f & 31) << 2;
            float4 v = Wf4[f];
            Wstg[k * WSTG_STRIDE + n4 + 0] = v.x;
            Wstg[k * WSTG_STRIDE + n4 + 1] = v.y;
            Wstg[k * WSTG_STRIDE + n4 + 2] = v.z;
            Wstg[k * WSTG_STRIDE + n4 + 3] = v.w;
        }
    }
    __syncthreads();
    // transpose-convert: Wt[n][k] = W[k][n] split into hi/lo (stride-129 reads conflict-free)
    {
        const float* Wstg = (const float*)(sm + SM_STG);
#pragma unroll
        for (int i = 0; i < 16; ++i) {
            int n = warp * 16 + i;
#pragma unroll
            for (int j = 0; j < 4; ++j) {
                int k = lane + 32 * j;
                float x = Wstg[k * WSTG_STRIDE + n];
                unsigned short h, l;
                split_bf16(x, h, l);
                u32 off = (u32)((n * AH_STRIDE + k) * 2);
                *(unsigned short*)(sm + SM_WH + off) = h;
                *(unsigned short*)(sm + SM_WL + off) = l;
            }
        }
    }
    __syncthreads();
}

// --- mainloop: warp = 32 rows x 64 cols; 3-pass bf16 emulated fp32 -----------
static __device__ __forceinline__ void mma_main(u32 smb, int warp, int lane,
                                                float C[2][8][4]) {
#pragma unroll
    for (int m = 0; m < 2; ++m)
#pragma unroll
        for (int n = 0; n < 8; ++n)
#pragma unroll
            for (int j = 0; j < 4; ++j) C[m][n][j] = 0.f;

    const int rowbase = (warp & 3) * 32;
    const int colbase = (warp >> 2) * 64;
    // A frag addresses: lanes 0-15 -> rows, col 0; lanes 16-31 -> rows, col 8
    const int ar = lane & 15;
    const int ac = (lane >> 4) << 3;
    const u32 aoffH = smb + SM_AH + (u32)(((rowbase + ar) * AH_STRIDE + ac) * 2);
    const u32 aoffL = aoffH + (SM_AL - SM_AH);
    // B frag addresses (Wt row-major [n][k]); mat = lane>>3 selects {n-half, k-half}
    const int mat = lane >> 3;
    const int bn  = colbase + ((mat >> 1) << 3) + (lane & 7);
    const int bk  = (mat & 1) << 3;
    const u32 boffH = smb + SM_WH + (u32)((bn * AH_STRIDE + bk) * 2);
    const u32 boffL = boffH + (SM_WL - SM_WH);

#pragma unroll
    for (int ks = 0; ks < 8; ++ks) {
        const u32 kb = (u32)(ks * 32);     // 16 bf16 = 32 bytes per k-step
        u32 ah[2][4], al[2][4], b[4][4];
        ldmatrix_x4(ah[0], aoffH + kb);
        ldmatrix_x4(ah[1], aoffH + 16 * ROWB + kb);
        ldmatrix_x4(al[0], aoffL + kb);
        ldmatrix_x4(al[1], aoffL + 16 * ROWB + kb);
#pragma unroll
        for (int q = 0; q < 4; ++q) ldmatrix_x4(b[q], boffH + (u32)(q * 16 * ROWB) + kb);
        // pass 1: Ah * Bh
#pragma unroll
        for (int m = 0; m < 2; ++m)
#pragma unroll
            for (int n = 0; n < 8; ++n)
                mma_bf16(C[m][n], ah[m], b[n >> 1][(n & 1) * 2], b[n >> 1][(n & 1) * 2 + 1]);
        // pass 2: Al * Bh
#pragma unroll
        for (int m = 0; m < 2; ++m)
#pragma unroll
            for (int n = 0; n < 8; ++n)
                mma_bf16(C[m][n], al[m], b[n >> 1][(n & 1) * 2], b[n >> 1][(n & 1) * 2 + 1]);
        // pass 3: Ah * Bl
#pragma unroll
        for (int q = 0; q < 4; ++q) ldmatrix_x4(b[q], boffL + (u32)(q * 16 * ROWB) + kb);
#pragma unroll
        for (int m = 0; m < 2; ++m)
#pragma unroll
            for (int n = 0; n < 8; ++n)
                mma_bf16(C[m][n], ah[m], b[n >> 1][(n & 1) * 2], b[n >> 1][(n & 1) * 2 + 1]);
    }
}

// --- stage C fragments -> smem rows (stride 132) -----------------------------
static __device__ __forceinline__ void mma_stage_d(char* sm, int warp, int lane,
                                                   float C[2][8][4]) {
    float* Ds = (float*)(sm + SM_STG);
    const int rowbase = (warp & 3) * 32;
    const int colbase = (warp >> 2) * 64;
    const int g  = lane >> 2;
    const int tq = lane & 3;
#pragma unroll
    for (int m = 0; m < 2; ++m) {
        int r0 = rowbase + m * 16 + g;
#pragma unroll
        for (int n = 0; n < 8; ++n) {
            int col = colbase + n * 8 + tq * 2;
            *(float2*)&Ds[r0 * DST_STRIDE + col]       = make_float2(C[m][n][0], C[m][n][1]);
            *(float2*)&Ds[(r0 + 8) * DST_STRIDE + col] = make_float2(C[m][n][2], C[m][n][3]);
        }
    }
    __syncthreads();
}

// ==================== Kernel 1: Y = X @ W (HMMA) =============================
extern "C" __global__ void __launch_bounds__(256, 1)
k_gemm_mma(const float* __restrict__ X, const float* __restrict__ W,
           float* __restrict__ Y, int totalRows) {
    extern __shared__ char sm[];
    u32 smb = smem_u32(sm);
    const int tid = threadIdx.x, lane = tid & 31, warp = tid >> 5;
    const size_t rowBase = (size_t)blockIdx.x * TM;
    int rowsValid = totalRows - (int)rowBase;
    if (rowsValid > TM) rowsValid = TM;

    mma_prologue(sm, X + rowBase * DD, rowsValid, W, tid, warp, lane);

    float C[2][8][4];
    mma_main(smb, warp, lane, C);
    mma_stage_d(sm, warp, lane, C);

    const float* Ds = (const float*)(sm + SM_STG);
#pragma unroll 4
    for (int rr = 0; rr < 16; ++rr) {
        int r = warp * 16 + rr;
        if (r < rowsValid) {
            size_t row = rowBase + r;
            float4 v = *(const float4*)&Ds[r * DST_STRIDE + lane * 4];
            reinterpret_cast<float4*>(Y + row * DD)[lane] = v;
        }
    }
}

// ==================== Kernel 2: bond update (HMMA + fused epilogue) ==========
extern "C" __global__ void __launch_bounds__(256, 1)
k_bond_mma(const float* __restrict__ bond, const float* __restrict__ W,
           const int* __restrict__ src_order, const int* __restrict__ tgt_order,
           const float* __restrict__ ln_g, const float* __restrict__ ln_b,
           float* __restrict__ out_bond) {
    extern __shared__ char sm[];
    u32 smb = smem_u32(sm);
    const int tid = threadIdx.x, lane = tid & 31, warp = tid >> 5;
    const size_t rowBase = (size_t)blockIdx.x * TM;   // 640000 / 128 = 5000 exact

    mma_prologue(sm, bond + rowBase * DD, TM, W, tid, warp, lane);

    float C[2][8][4];
    mma_main(smb, warp, lane, C);
    mma_stage_d(sm, warp, lane, C);

    const float* Ds = (const float*)(sm + SM_STG);
    const float4 gv = reinterpret_cast<const float4*>(ln_g)[lane];
    const float4 bv = reinterpret_cast<const float4*>(ln_b)[lane];

#pragma unroll 4
    for (int rr = 0; rr < 16; ++rr) {
        int r = warp * 16 + rr;
        size_t row = rowBase + r;
        int b = (int)(row / NE);
        int e = (int)(row - (size_t)b * NE);
        int so = __ldg(src_order + e);
        int to = __ldg(tgt_order + e);
        float4 sp = reinterpret_cast<const float4*>(g_sproj + ((size_t)b * NSRC + so) * DD)[lane];
        float4 tp = reinterpret_cast<const float4*>(g_tproj + ((size_t)b * NTGT + to) * DD)[lane];
        float4 d  = *(const float4*)&Ds[r * DST_STRIDE + lane * 4];

        // residual bond value reconstructed from hi+lo bf16 tiles (err ~8e-6)
        u32 o = (u32)((r * AH_STRIDE + lane * 4) * 2);
        u64 hp = *(const u64*)(sm + SM_AH + o);
        u64 lp = *(const u64*)(sm + SM_AL + o);
        float x0 = __bfloat162float(__ushort_as_bfloat16((unsigned short)(hp)))       +
                   __bfloat162float(__ushort_as_bfloat16((unsigned short)(lp)));
        float x1 = __bfloat162float(__ushort_as_bfloat16((unsigned short)(hp >> 16))) +
                   __bfloat162float(__ushort_as_bfloat16((unsigned short)(lp >> 16)));
        float x2 = __bfloat162float(__ushort_as_bfloat16((unsigned short)(hp >> 32))) +
                   __bfloat162float(__ushort_as_bfloat16((unsigned short)(lp >> 32)));
        float x3 = __bfloat162float(__ushort_as_bfloat16((unsigned short)(hp >> 48))) +
                   __bfloat162float(__ushort_as_bfloat16((unsigned short)(lp >> 48)));

        float z0 = silu_f(d.x + sp.x + tp.x);
        float z1 = silu_f(d.y + sp.y + tp.y);
        float z2 = silu_f(d.z + sp.z + tp.z);
        float z3 = silu_f(d.w + sp.w + tp.w);

        float mean, rstd;
        warp_ln_stats(z0, z1, z2, z3, mean, rstd);

        float4 db;
        db.x = (z0 - mean) * rstd * gv.x + bv.x;
        db.y = (z1 - mean) * rstd * gv.y + bv.y;
        db.z = (z2 - mean) * rstd * gv.z + bv.z;
        db.w = (z3 - mean) * rstd * gv.w + bv.w;

        reinterpret_cast<float4*>(g_dbond + row * DD)[lane] = db;
        float4 ov = make_float4(x0 + db.x, x1 + db.y, x2 + db.z, x3 + db.w);
        reinterpret_cast<float4*>(out_bond + row * DD)[lane] = ov;
    }
}

// ==================== Kernel 3: node update (FFMA2 scalar path) ==============
#define ROWS_PER_WARP 8
#define ROWS_PER_BLK  64
#define XT_STRIDE     66
#define SMEM_FLOATS   (DD * DD + DD * XT_STRIDE)

static __device__ __forceinline__ u64 dup_f32x2(float w) {
    u64 r; asm("mov.b64 %0, {%1, %1};" : "=l"(r) : "f"(w)); return r;
}
static __device__ __forceinline__ u64 ffma2(u64 a, u64 b, u64 c) {
    u64 d; asm("fma.rn.f32x2 %0, %1, %2, %3;" : "=l"(d) : "l"(a), "l"(b), "l"(c)); return d;
}
static __device__ __forceinline__ void unpack2(u64 v, float& lo, float& hi) {
    asm("mov.b64 {%0, %1}, %2;" : "=f"(lo), "=f"(hi) : "l"(v));
}
static __device__ __forceinline__ void load_w_smem(float* Ws, const float* __restrict__ W, int tid) {
    const float4* src = reinterpret_cast<const float4*>(W);
    float4* dst = reinterpret_cast<float4*>(Ws);
#pragma unroll
    for (int i = 0; i < 16; ++i) dst[tid + i * 256] = src[tid + i * 256];
}
static __device__ __forceinline__ void gemm_tile2(const float* __restrict__ Ws,
                                                  const float* __restrict__ XsT,
                                                  int wrow0, int lane,
                                                  float accf[ROWS_PER_WARP][4]) {
    u64 acc2[4][4];
#pragma unroll
    for (int p = 0; p < 4; ++p)
#pragma unroll
        for (int c = 0; c < 4; ++c) acc2[p][c] = 0ull;
#pragma unroll 4
    for (int k = 0; k < DD; ++k) {
        float4 wv = reinterpret_cast<const float4*>(Ws + k * DD)[lane];
        u64 w0 = dup_f32x2(wv.x), w1 = dup_f32x2(wv.y);
        u64 w2 = dup_f32x2(wv.z), w3 = dup_f32x2(wv.w);
        const float* xb = XsT + k * XT_STRIDE + wrow0;
#pragma unroll
        for (int p = 0; p < 4; ++p) {
            u64 xp = *reinterpret_cast<const u64*>(xb + 2 * p);
            acc2[p][0] = ffma2(xp, w0, acc2[p][0]);
            acc2[p][1] = ffma2(xp, w1, acc2[p][1]);
            acc2[p][2] = ffma2(xp, w2, acc2[p][2]);
            acc2[p][3] = ffma2(xp, w3, acc2[p][3]);
        }
    }
#pragma unroll
    for (int p = 0; p < 4; ++p)
#pragma unroll
        for (int c = 0; c < 4; ++c)
            unpack2(acc2[p][c], accf[2 * p][c], accf[2 * p + 1][c]);
}

extern "C" __global__ void __launch_bounds__(256, 2)
k_node(const float* __restrict__ tgt, const float* __restrict__ W,
       const float* __restrict__ coef, const int* __restrict__ edge_order,
       const float* __restrict__ ln_g, const float* __restrict__ ln_b,
       float* __restrict__ out_tgt) {
    extern __shared__ float smf[];
    float* Ws  = smf;
    float* XsT = smf + DD * DD;
    const int tid = threadIdx.x, lane = tid & 31, warp = tid >> 5;
    const size_t rowBase = (size_t)blockIdx.x * ROWS_PER_BLK;

    load_w_smem(Ws, W, tid);

#pragma unroll
    for (int r = 0; r < ROWS_PER_WARP; ++r) {
        int rl = warp * ROWS_PER_WARP + r;
        size_t row = rowBase + rl;
        int b = (int)(row / NTGT);
        int t = (int)(row - (size_t)b * NTGT);
        float4 acc4 = make_float4(0.f, 0.f, 0.f, 0.f);
#pragma unroll
        for (int k = 0; k < NK; ++k) {
            int e   = __ldg(edge_order + (size_t)t * NK + k);
            float c = __ldg(coef       + (size_t)t * NK + k);
            float4 v = reinterpret_cast<const float4*>(g_dbond + ((size_t)b * NE + e) * DD)[lane];
            acc4.x += c * v.x; acc4.y += c * v.y;
            acc4.z += c * v.z; acc4.w += c * v.w;
        }
        const float inv_k = 1.0f / NK;
        int k0 = lane * 4;
        XsT[(k0 + 0) * XT_STRIDE + rl] = acc4.x * inv_k;
        XsT[(k0 + 1) * XT_STRIDE + rl] = acc4.y * inv_k;
        XsT[(k0 + 2) * XT_STRIDE + rl] = acc4.z * inv_k;
        XsT[(k0 + 3) * XT_STRIDE + rl] = acc4.w * inv_k;
    }
    __syncthreads();

    float accf[ROWS_PER_WARP][4];
    gemm_tile2(Ws, XsT, warp * ROWS_PER_WARP, lane, accf);

    const float4 gv = reinterpret_cast<const float4*>(ln_g)[lane];
    const float4 bv = reinterpret_cast<const float4*>(ln_b)[lane];

#pragma unroll
    for (int r = 0; r < ROWS_PER_WARP; ++r) {
        size_t row = rowBase + warp * ROWS_PER_WARP + r;
        float4 t2 = reinterpret_cast<const float4*>(g_tproj2 + row * DD)[lane];

        float z0 = silu_f(accf[r][0] + t2.x);
        float z1 = silu_f(accf[r][1] + t2.y);
        float z2 = silu_f(accf[r][2] + t2.z);
        float z3 = silu_f(accf[r][3] + t2.w);

        float mean, rstd;
        warp_ln_stats(z0, z1, z2, z3, mean, rstd);

        float4 d;
        d.x = (z0 - mean) * rstd * gv.x + bv.x;
        d.y = (z1 - mean) * rstd * gv.y + bv.y;
        d.z = (z2 - mean) * rstd * gv.z + bv.z;
        d.w = (z3 - mean) * rstd * gv.w + bv.w;

        float4 tin = reinterpret_cast<const float4*>(tgt + row * DD)[lane];
        float4 ov = make_float4(tin.x + d.x, tin.y + d.y, tin.z + d.z, tin.w + d.w);
        reinterpret_cast<float4*>(out_tgt + row * DD)[lane] = ov;
    }
}

// ==================== launch =================================================
extern "C" void kernel_launch(void* const* d_in, const int* in_sizes, int n_in,
                              void* d_out, int out_size) {
    const float* bond   = (const float*)d_in[0];
    const float* src    = (const float*)d_in[1];
    const float* tgt    = (const float*)d_in[2];
    const float* W_s2e  = (const float*)d_in[3];
    const float* W_t2e  = (const float*)d_in[4];
    const float* W_e2e  = (const float*)d_in[5];
    const float* ln1_g  = (const float*)d_in[6];
    const float* ln1_b  = (const float*)d_in[7];
    const float* W_e2t  = (const float*)d_in[8];
    const float* W_t2t  = (const float*)d_in[9];
    const float* ln2_g  = (const float*)d_in[10];
    const float* ln2_b  = (const float*)d_in[11];
    const float* coef   = (const float*)d_in[12];
    const int*   so     = (const int*)d_in[13];
    const int*   to     = (const int*)d_in[14];
    const int*   eo     = (const int*)d_in[15];

    float* out = (float*)d_out;
    float* out_bond = out;
    float* out_src  = out + (size_t)NB * NE * DD;
    float* out_tgt  = out_src + (size_t)NB * NSRC * DD;

    cudaFuncSetAttribute(k_gemm_mma, cudaFuncAttributeMaxDynamicSharedMemorySize, SM_TOTAL);
    cudaFuncSetAttribute(k_bond_mma, cudaFuncAttributeMaxDynamicSharedMemorySize, SM_TOTAL);
    const size_t smemN = SMEM_FLOATS * sizeof(float);
    cudaFuncSetAttribute(k_node, cudaFuncAttributeMaxDynamicSharedMemorySize, (int)smemN);

    float *sproj, *tproj, *tproj2;
    cudaGetSymbolAddress((void**)&sproj,  g_sproj);
    cudaGetSymbolAddress((void**)&tproj,  g_tproj);
    cudaGetSymbolAddress((void**)&tproj2, g_tproj2);

    cudaMemcpyAsync(out_src, src, (size_t)NB * NSRC * DD * sizeof(float),
                    cudaMemcpyDeviceToDevice);

    const int rowsNode = NB * NTGT;                       // 40000
    const int rowsBond = NB * NE;                         // 640000
    const int gridNode = (rowsNode + TM - 1) / TM;        // 313
    const int gridBond = rowsBond / TM;                   // 5000

    k_gemm_mma<<<gridNode, 256, SM_TOTAL>>>(src, W_s2e, sproj,  rowsNode);
    k_gemm_mma<<<gridNode, 256, SM_TOTAL>>>(tgt, W_t2e, tproj,  rowsNode);
    k_gemm_mma<<<gridNode, 256, SM_TOTAL>>>(tgt, W_t2t, tproj2, rowsNode);

    k_bond_mma<<<gridBond, 256, SM_TOTAL>>>(bond, W_e2e, so, to, ln1_g, ln1_b, out_bond);

    k_node<<<rowsNode / ROWS_PER_BLK, 256, smemN>>>(tgt, W_e2t, coef, eo,
                                                    ln2_g, ln2_b, out_tgt);
}

// round 13
// speedup vs baseline: 1.3794x; 1.3794x over previous
#include <cuda_runtime.h>
#include <cuda_bf16.h>
#include <cstdint>
#include <cstddef>

// Problem constants
#define DD   128
#define NB   4
#define NSRC 10000
#define NTGT 10000
#define NE   160000
#define NK   16

// Scratch (device globals: allocation-free rule)
__device__ float g_sproj [NB * NSRC * DD];
__device__ float g_tproj [NB * NTGT * DD];
__device__ float g_tproj2[NB * NTGT * DD];
__device__ float g_dbond [NB * NE * DD];

typedef unsigned long long u64;
typedef unsigned int       u32;
typedef unsigned short     u16;

#define AH_STRIDE 136                    // bf16 elems per row (272B, conflict-free ldmatrix)
#define ROWB      (AH_STRIDE * 2)        // 272 bytes per tile row
#define WTILE_B   (DD * AH_STRIDE * 2)   // 34816 bytes: one 128x128 padded bf16 tile

// Precomputed W_e2e^T hi/lo tile images (exact smem layout, 16B aligned)
__device__ uint4 g_whT[WTILE_B / 16];
__device__ uint4 g_wlT[WTILE_B / 16];

static __device__ __forceinline__ u32 smem_u32(const void* p) {
    u32 a;
    asm("{ .reg .u64 t; cvta.to.shared.u64 t, %1; cvt.u32.u64 %0, t; }" : "=r"(a) : "l"(p));
    return a;
}

static __device__ __forceinline__ void ldmatrix_x4(u32* r, u32 addr) {
    asm volatile("ldmatrix.sync.aligned.m8n8.x4.shared.b16 {%0,%1,%2,%3}, [%4];"
                 : "=r"(r[0]), "=r"(r[1]), "=r"(r[2]), "=r"(r[3]) : "r"(addr));
}

static __device__ __forceinline__ void mma_bf16(float* c, const u32* a, u32 b0, u32 b1) {
    asm volatile("mma.sync.aligned.m16n8k16.row.col.f32.bf16.bf16.f32 "
                 "{%0,%1,%2,%3}, {%4,%5,%6,%7}, {%8,%9}, {%0,%1,%2,%3};"
                 : "+f"(c[0]), "+f"(c[1]), "+f"(c[2]), "+f"(c[3])
                 : "r"(a[0]), "r"(a[1]), "r"(a[2]), "r"(a[3]), "r"(b0), "r"(b1));
}

static __device__ __forceinline__ void split_bf16(float x, u16& h, u16& l) {
    __nv_bfloat16 hb = __float2bfloat16_rn(x);
    float xh = __bfloat162float(hb);
    __nv_bfloat16 lb = __float2bfloat16_rn(x - xh);
    h = __bfloat16_as_ushort(hb);
    l = __bfloat16_as_ushort(lb);
}

static __device__ __forceinline__ float silu_f(float x) {
    return x / (1.0f + __expf(-x));
}

// ==================== k_prep: W_e2e -> transposed hi/lo tile images ==========
extern "C" __global__ void k_prep(const float* __restrict__ W) {
    int idx = blockIdx.x * 256 + threadIdx.x;        // 16384 total
    int k = idx >> 7, n = idx & 127;
    float x = W[k * DD + n];
    u16 h, l;
    split_bf16(x, h, l);
    u32 off = (u32)((n * AH_STRIDE + k) * 2);
    *(u16*)((char*)g_whT + off) = h;
    *(u16*)((char*)g_wlT + off) = l;
}

// ==================== k_bond_mma: 256 rows/CTA, 512 threads ==================
// smem layout
#define B_SM_AH   0
#define B_ATILE   (256 * AH_STRIDE * 2)     // 69632
#define B_SM_AL   69632
#define B_SM_WH   139264
#define B_SM_WL   174080
#define B_SM_TOT  208896

static __device__ __forceinline__ void warpquad_ln(float s, float q,
                                                   float& mean, float& rstd) {
    s += __shfl_xor_sync(0xffffffffu, s, 1);
    s += __shfl_xor_sync(0xffffffffu, s, 2);
    q += __shfl_xor_sync(0xffffffffu, q, 1);
    q += __shfl_xor_sync(0xffffffffu, q, 2);
    mean = s * (1.0f / DD);
    float var = q * (1.0f / DD) - mean * mean;
    rstd = rsqrtf(var + 1e-5f);
}

extern "C" __global__ void __launch_bounds__(512, 1)
k_bond_mma(const float* __restrict__ bond,
           const int* __restrict__ src_order, const int* __restrict__ tgt_order,
           const float* __restrict__ ln_g, const float* __restrict__ ln_b,
           float* __restrict__ out_bond) {
    extern __shared__ char sm[];
    u32 smb = smem_u32(sm);
    const int tid = threadIdx.x, lane = tid & 31, warp = tid >> 5;   // 16 warps
    const size_t rowBase = (size_t)blockIdx.x * 256;                 // batch-aligned (160000%256==0? 160000/256=625 ✓)

    // ---- prologue ----
    // A: load 256x128 fp32, split into hi/lo bf16 tiles
    {
        const float4* Xf4 = (const float4*)(bond + rowBase * DD);
#pragma unroll
        for (int i = 0; i < 16; ++i) {
            int f = tid + i * 512;           // 8192 float4
            int r = f >> 5, c4 = (f & 31) << 2;
            float4 v = Xf4[f];
            u16 h0, l0, h1, l1, h2, l2, h3, l3;
            split_bf16(v.x, h0, l0); split_bf16(v.y, h1, l1);
            split_bf16(v.z, h2, l2); split_bf16(v.w, h3, l3);
            u64 hp = (u64)h0 | ((u64)h1 << 16) | ((u64)h2 << 32) | ((u64)h3 << 48);
            u64 lp = (u64)l0 | ((u64)l1 << 16) | ((u64)l2 << 32) | ((u64)l3 << 48);
            u32 off = (u32)((r * AH_STRIDE + c4) * 2);
            *(u64*)(sm + B_SM_AH + off) = hp;
            *(u64*)(sm + B_SM_AL + off) = lp;
        }
    }
    // W: straight copy of precomputed tile images (2176 uint4 each)
    {
        uint4* wh = (uint4*)(sm + B_SM_WH);
        uint4* wl = (uint4*)(sm + B_SM_WL);
        for (int i = tid; i < WTILE_B / 16; i += 512) {
            wh[i] = g_whT[i];
            wl[i] = g_wlT[i];
        }
    }
    __syncthreads();

    // ---- mainloop: warp owns rows 16*warp .. 16*warp+15, all 128 cols ----
    float C[16][4];
#pragma unroll
    for (int n = 0; n < 16; ++n)
#pragma unroll
        for (int j = 0; j < 4; ++j) C[n][j] = 0.f;

    const int ar = lane & 15;
    const int ac = (lane >> 4) << 3;
    const u32 aH = smb + B_SM_AH + (u32)(((16 * warp + ar) * AH_STRIDE + ac) * 2);
    const u32 aL = aH + (B_SM_AL - B_SM_AH);
    const int mat = lane >> 3;
    const int bn  = ((mat >> 1) << 3) + (lane & 7);
    const int bk  = (mat & 1) << 3;
    const u32 bH = smb + B_SM_WH + (u32)((bn * AH_STRIDE + bk) * 2);
    const u32 bL = bH + (B_SM_WL - B_SM_WH);

#pragma unroll
    for (int ks = 0; ks < 8; ++ks) {
        const u32 kb = (u32)(ks * 32);
        u32 ah[4], al[4];
        ldmatrix_x4(ah, aH + kb);
        ldmatrix_x4(al, aL + kb);
#pragma unroll
        for (int q = 0; q < 8; ++q) {
            u32 b4[4];
            ldmatrix_x4(b4, bH + (u32)(q * 16 * ROWB) + kb);
            mma_bf16(C[2 * q],     ah, b4[0], b4[1]);
            mma_bf16(C[2 * q + 1], ah, b4[2], b4[3]);
            mma_bf16(C[2 * q],     al, b4[0], b4[1]);
            mma_bf16(C[2 * q + 1], al, b4[2], b4[3]);
            u32 c4r[4];
            ldmatrix_x4(c4r, bL + (u32)(q * 16 * ROWB) + kb);
            mma_bf16(C[2 * q],     ah, c4r[0], c4r[1]);
            mma_bf16(C[2 * q + 1], ah, c4r[2], c4r[3]);
        }
    }

    // ---- epilogue: direct from fragments; LN per row within a lane-quad ----
    const int lrow0 = 16 * warp + (lane >> 2);
    const int lrow1 = lrow0 + 8;
    const size_t grow0 = rowBase + lrow0;
    const size_t grow1 = rowBase + lrow1;
    const int b = (int)(rowBase / NE);
    const int e0 = (int)(grow0 - (size_t)b * NE);
    const int e1 = (int)(grow1 - (size_t)b * NE);
    const int so0 = __ldg(src_order + e0), to0 = __ldg(tgt_order + e0);
    const int so1 = __ldg(src_order + e1), to1 = __ldg(tgt_order + e1);
    const float* sp0 = g_sproj + ((size_t)b * NSRC + so0) * DD;
    const float* tp0 = g_tproj + ((size_t)b * NTGT + to0) * DD;
    const float* sp1 = g_sproj + ((size_t)b * NSRC + so1) * DD;
    const float* tp1 = g_tproj + ((size_t)b * NTGT + to1) * DD;
    const int c2 = (lane & 3) * 2;

    float s0 = 0.f, q0 = 0.f, s1 = 0.f, q1 = 0.f;
#pragma unroll
    for (int n = 0; n < 16; ++n) {
        int col = n * 8 + c2;
        float2 a0 = *(const float2*)(sp0 + col);
        float2 b0 = *(const float2*)(tp0 + col);
        float2 a1 = *(const float2*)(sp1 + col);
        float2 b1 = *(const float2*)(tp1 + col);
        float z;
        z = silu_f(C[n][0] + a0.x + b0.x); C[n][0] = z; s0 += z; q0 += z * z;
        z = silu_f(C[n][1] + a0.y + b0.y); C[n][1] = z; s0 += z; q0 += z * z;
        z = silu_f(C[n][2] + a1.x + b1.x); C[n][2] = z; s1 += z; q1 += z * z;
        z = silu_f(C[n][3] + a1.y + b1.y); C[n][3] = z; s1 += z; q1 += z * z;
    }
    float m0, r0, m1, r1;
    warpquad_ln(s0, q0, m0, r0);
    warpquad_ln(s1, q1, m1, r1);

    float* db_out0 = g_dbond + grow0 * DD;
    float* db_out1 = g_dbond + grow1 * DD;
    float* ob0 = out_bond + grow0 * DD;
    float* ob1 = out_bond + grow1 * DD;

#pragma unroll
    for (int n = 0; n < 16; ++n) {
        int col = n * 8 + c2;
        float2 gg = *(const float2*)(ln_g + col);
        float2 bb = *(const float2*)(ln_b + col);
        float2 d0, d1;
        d0.x = (C[n][0] - m0) * r0 * gg.x + bb.x;
        d0.y = (C[n][1] - m0) * r0 * gg.y + bb.y;
        d1.x = (C[n][2] - m1) * r1 * gg.x + bb.x;
        d1.y = (C[n][3] - m1) * r1 * gg.y + bb.y;
        *(float2*)(db_out0 + col) = d0;
        *(float2*)(db_out1 + col) = d1;
        // residual bond from hi+lo tiles (err ~8e-6)
        u32 o0 = (u32)((lrow0 * AH_STRIDE + col) * 2);
        u32 o1 = (u32)((lrow1 * AH_STRIDE + col) * 2);
        u32 h0 = *(const u32*)(sm + B_SM_AH + o0), l0v = *(const u32*)(sm + B_SM_AL + o0);
        u32 h1 = *(const u32*)(sm + B_SM_AH + o1), l1v = *(const u32*)(sm + B_SM_AL + o1);
        float2 x0, x1;
        x0.x = __bfloat162float(__ushort_as_bfloat16((u16)h0))         +
               __bfloat162float(__ushort_as_bfloat16((u16)l0v));
        x0.y = __bfloat162float(__ushort_as_bfloat16((u16)(h0 >> 16))) +
               __bfloat162float(__ushort_as_bfloat16((u16)(l0v >> 16)));
        x1.x = __bfloat162float(__ushort_as_bfloat16((u16)h1))         +
               __bfloat162float(__ushort_as_bfloat16((u16)l1v));
        x1.y = __bfloat162float(__ushort_as_bfloat16((u16)(h1 >> 16))) +
               __bfloat162float(__ushort_as_bfloat16((u16)(l1v >> 16)));
        *(float2*)(ob0 + col) = make_float2(x0.x + d0.x, x0.y + d0.y);
        *(float2*)(ob1 + col) = make_float2(x1.x + d1.x, x1.y + d1.y);
    }
}

// ==================== small GEMMs: validated TM=128 HMMA path ================
#define TM 128
#define SM_AH   0
#define SM_AL   34816
#define SM_WH   69632
#define SM_WL   104448
#define SM_STG  139264
#define SM_TOTAL 206848
#define WSTG_STRIDE 129
#define DST_STRIDE  132

static __device__ __forceinline__ void mma_prologue(char* sm,
                                                    const float* __restrict__ Xrow0, int rowsValid,
                                                    const float* __restrict__ W,
                                                    int tid, int warp, int lane) {
    {
        const float4* Xf4 = (const float4*)Xrow0;
#pragma unroll
        for (int i = 0; i < 16; ++i) {
            int f = tid + i * 256;
            int r = f >> 5, c4 = (f & 31) << 2;
            int rr = (r < rowsValid) ? r : (rowsValid - 1);
            float4 v = Xf4[rr * 32 + (f & 31)];
            u16 h0, l0, h1, l1, h2, l2, h3, l3;
            split_bf16(v.x, h0, l0); split_bf16(v.y, h1, l1);
            split_bf16(v.z, h2, l2); split_bf16(v.w, h3, l3);
            u64 hp = (u64)h0 | ((u64)h1 << 16) | ((u64)h2 << 32) | ((u64)h3 << 48);
            u64 lp = (u64)l0 | ((u64)l1 << 16) | ((u64)l2 << 32) | ((u64)l3 << 48);
            u32 off = (u32)((r * AH_STRIDE + c4) * 2);
            *(u64*)(sm + SM_AH + off) = hp;
            *(u64*)(sm + SM_AL + off) = lp;
        }
    }
    {
        float* Wstg = (float*)(sm + SM_STG);
        const float4* Wf4 = (const float4*)W;
#pragma unroll
        for (int i = 0; i < 16; ++i) {
            int f = tid + i * 256;
            int k = f >> 5, n4 = (f & 31) << 2;
            float4 v = Wf4[f];
            Wstg[k * WSTG_STRIDE + n4 + 0] = v.x;
            Wstg[k * WSTG_STRIDE + n4 + 1] = v.y;
            Wstg[k * WSTG_STRIDE + n4 + 2] = v.z;
            Wstg[k * WSTG_STRIDE + n4 + 3] = v.w;
        }
    }
    __syncthreads();
    {
        const float* Wstg = (const float*)(sm + SM_STG);
#pragma unroll
        for (int i = 0; i < 16; ++i) {
            int n = warp * 16 + i;
#pragma unroll
            for (int j = 0; j < 4; ++j) {
                int k = lane + 32 * j;
                float x = Wstg[k * WSTG_STRIDE + n];
                u16 h, l;
                split_bf16(x, h, l);
                u32 off = (u32)((n * AH_STRIDE + k) * 2);
                *(u16*)(sm + SM_WH + off) = h;
                *(u16*)(sm + SM_WL + off) = l;
            }
        }
    }
    __syncthreads();
}

static __device__ __forceinline__ void mma_main128(u32 smb, int warp, int lane,
                                                   float C[2][8][4]) {
#pragma unroll
    for (int m = 0; m < 2; ++m)
#pragma unroll
        for (int n = 0; n < 8; ++n)
#pragma unroll
            for (int j = 0; j < 4; ++j) C[m][n][j] = 0.f;

    const int rowbase = (warp & 3) * 32;
    const int colbase = (warp >> 2) * 64;
    const int ar = lane & 15;
    const int ac = (lane >> 4) << 3;
    const u32 aoffH = smb + SM_AH + (u32)(((rowbase + ar) * AH_STRIDE + ac) * 2);
    const u32 aoffL = aoffH + (SM_AL - SM_AH);
    const int mat = lane >> 3;
    const int bn  = colbase + ((mat >> 1) << 3) + (lane & 7);
    const int bk  = (mat & 1) << 3;
    const u32 boffH = smb + SM_WH + (u32)((bn * AH_STRIDE + bk) * 2);
    const u32 boffL = boffH + (SM_WL - SM_WH);

#pragma unroll
    for (int ks = 0; ks < 8; ++ks) {
        const u32 kb = (u32)(ks * 32);
        u32 ah[2][4], al[2][4], b[4][4];
        ldmatrix_x4(ah[0], aoffH + kb);
        ldmatrix_x4(ah[1], aoffH + 16 * ROWB + kb);
        ldmatrix_x4(al[0], aoffL + kb);
        ldmatrix_x4(al[1], aoffL + 16 * ROWB + kb);
#pragma unroll
        for (int q = 0; q < 4; ++q) ldmatrix_x4(b[q], boffH + (u32)(q * 16 * ROWB) + kb);
#pragma unroll
        for (int m = 0; m < 2; ++m)
#pragma unroll
            for (int n = 0; n < 8; ++n)
                mma_bf16(C[m][n], ah[m], b[n >> 1][(n & 1) * 2], b[n >> 1][(n & 1) * 2 + 1]);
#pragma unroll
        for (int m = 0; m < 2; ++m)
#pragma unroll
            for (int n = 0; n < 8; ++n)
                mma_bf16(C[m][n], al[m], b[n >> 1][(n & 1) * 2], b[n >> 1][(n & 1) * 2 + 1]);
#pragma unroll
        for (int q = 0; q < 4; ++q) ldmatrix_x4(b[q], boffL + (u32)(q * 16 * ROWB) + kb);
#pragma unroll
        for (int m = 0; m < 2; ++m)
#pragma unroll
            for (int n = 0; n < 8; ++n)
                mma_bf16(C[m][n], ah[m], b[n >> 1][(n & 1) * 2], b[n >> 1][(n & 1) * 2 + 1]);
    }
}

extern "C" __global__ void __launch_bounds__(256, 1)
k_gemm_mma(const float* __restrict__ X, const float* __restrict__ W,
           float* __restrict__ Y, int totalRows) {
    extern __shared__ char sm[];
    u32 smb = smem_u32(sm);
    const int tid = threadIdx.x, lane = tid & 31, warp = tid >> 5;
    const size_t rowBase = (size_t)blockIdx.x * TM;
    int rowsValid = totalRows - (int)rowBase;
    if (rowsValid > TM) rowsValid = TM;

    mma_prologue(sm, X + rowBase * DD, rowsValid, W, tid, warp, lane);

    float C[2][8][4];
    mma_main128(smb, warp, lane, C);

    // stage D then write
    {
        float* Ds = (float*)(sm + SM_STG);
        const int rowbase = (warp & 3) * 32;
        const int colbase = (warp >> 2) * 64;
        const int g  = lane >> 2;
        const int tq = lane & 3;
        __syncthreads();
#pragma unroll
        for (int m = 0; m < 2; ++m) {
            int r0 = rowbase + m * 16 + g;
#pragma unroll
            for (int n = 0; n < 8; ++n) {
                int col = colbase + n * 8 + tq * 2;
                *(float2*)&Ds[r0 * DST_STRIDE + col]       = make_float2(C[m][n][0], C[m][n][1]);
                *(float2*)&Ds[(r0 + 8) * DST_STRIDE + col] = make_float2(C[m][n][2], C[m][n][3]);
            }
        }
        __syncthreads();
    }
    const float* Ds = (const float*)(sm + SM_STG);
#pragma unroll 4
    for (int rr = 0; rr < 16; ++rr) {
        int r = warp * 16 + rr;
        if (r < rowsValid) {
            size_t row = rowBase + r;
            float4 v = *(const float4*)&Ds[r * DST_STRIDE + lane * 4];
            reinterpret_cast<float4*>(Y + row * DD)[lane] = v;
        }
    }
}

// ==================== Kernel 3: node update (FFMA2 scalar path) ==============
#define ROWS_PER_WARP 8
#define ROWS_PER_BLK  64
#define XT_STRIDE     66
#define SMEM_FLOATS   (DD * DD + DD * XT_STRIDE)

static __device__ __forceinline__ u64 dup_f32x2(float w) {
    u64 r; asm("mov.b64 %0, {%1, %1};" : "=l"(r) : "f"(w)); return r;
}
static __device__ __forceinline__ u64 ffma2(u64 a, u64 b, u64 c) {
    u64 d; asm("fma.rn.f32x2 %0, %1, %2, %3;" : "=l"(d) : "l"(a), "l"(b), "l"(c)); return d;
}
static __device__ __forceinline__ void unpack2(u64 v, float& lo, float& hi) {
    asm("mov.b64 {%0, %1}, %2;" : "=f"(lo), "=f"(hi) : "l"(v));
}
static __device__ __forceinline__ void load_w_smem(float* Ws, const float* __restrict__ W, int tid) {
    const float4* src = reinterpret_cast<const float4*>(W);
    float4* dst = reinterpret_cast<float4*>(Ws);
#pragma unroll
    for (int i = 0; i < 16; ++i) dst[tid + i * 256] = src[tid + i * 256];
}
static __device__ __forceinline__ void gemm_tile2(const float* __restrict__ Ws,
                                                  const float* __restrict__ XsT,
                                                  int wrow0, int lane,
                                                  float accf[ROWS_PER_WARP][4]) {
    u64 acc2[4][4];
#pragma unroll
    for (int p = 0; p < 4; ++p)
#pragma unroll
        for (int c = 0; c < 4; ++c) acc2[p][c] = 0ull;
#pragma unroll 4
    for (int k = 0; k < DD; ++k) {
        float4 wv = reinterpret_cast<const float4*>(Ws + k * DD)[lane];
        u64 w0 = dup_f32x2(wv.x), w1 = dup_f32x2(wv.y);
        u64 w2 = dup_f32x2(wv.z), w3 = dup_f32x2(wv.w);
        const float* xb = XsT + k * XT_STRIDE + wrow0;
#pragma unroll
        for (int p = 0; p < 4; ++p) {
            u64 xp = *reinterpret_cast<const u64*>(xb + 2 * p);
            acc2[p][0] = ffma2(xp, w0, acc2[p][0]);
            acc2[p][1] = ffma2(xp, w1, acc2[p][1]);
            acc2[p][2] = ffma2(xp, w2, acc2[p][2]);
            acc2[p][3] = ffma2(xp, w3, acc2[p][3]);
        }
    }
#pragma unroll
    for (int p = 0; p < 4; ++p)
#pragma unroll
        for (int c = 0; c < 4; ++c)
            unpack2(acc2[p][c], accf[2 * p][c], accf[2 * p + 1][c]);
}

static __device__ __forceinline__ void warp_ln_stats(float z0, float z1, float z2, float z3,
                                                     float& mean, float& rstd) {
    float s  = z0 + z1 + z2 + z3;
    float s2 = z0 * z0 + z1 * z1 + z2 * z2 + z3 * z3;
#pragma unroll
    for (int off = 16; off; off >>= 1) {
        s  += __shfl_xor_sync(0xffffffffu, s,  off);
        s2 += __shfl_xor_sync(0xffffffffu, s2, off);
    }
    mean = s * (1.0f / DD);
    float var = s2 * (1.0f / DD) - mean * mean;
    rstd = rsqrtf(var + 1e-5f);
}

extern "C" __global__ void __launch_bounds__(256, 2)
k_node(const float* __restrict__ tgt, const float* __restrict__ W,
       const float* __restrict__ coef, const int* __restrict__ edge_order,
       const float* __restrict__ ln_g, const float* __restrict__ ln_b,
       float* __restrict__ out_tgt) {
    extern __shared__ float smf[];
    float* Ws  = smf;
    float* XsT = smf + DD * DD;
    const int tid = threadIdx.x, lane = tid & 31, warp = tid >> 5;
    const size_t rowBase = (size_t)blockIdx.x * ROWS_PER_BLK;

    load_w_smem(Ws, W, tid);

#pragma unroll
    for (int r = 0; r < ROWS_PER_WARP; ++r) {
        int rl = warp * ROWS_PER_WARP + r;
        size_t row = rowBase + rl;
        int b = (int)(row / NTGT);
        int t = (int)(row - (size_t)b * NTGT);
        float4 acc4 = make_float4(0.f, 0.f, 0.f, 0.f);
#pragma unroll
        for (int k = 0; k < NK; ++k) {
            int e   = __ldg(edge_order + (size_t)t * NK + k);
            float c = __ldg(coef       + (size_t)t * NK + k);
            float4 v = reinterpret_cast<const float4*>(g_dbond + ((size_t)b * NE + e) * DD)[lane];
            acc4.x += c * v.x; acc4.y += c * v.y;
            acc4.z += c * v.z; acc4.w += c * v.w;
        }
        const float inv_k = 1.0f / NK;
        int k0 = lane * 4;
        XsT[(k0 + 0) * XT_STRIDE + rl] = acc4.x * inv_k;
        XsT[(k0 + 1) * XT_STRIDE + rl] = acc4.y * inv_k;
        XsT[(k0 + 2) * XT_STRIDE + rl] = acc4.z * inv_k;
        XsT[(k0 + 3) * XT_STRIDE + rl] = acc4.w * inv_k;
    }
    __syncthreads();

    float accf[ROWS_PER_WARP][4];
    gemm_tile2(Ws, XsT, warp * ROWS_PER_WARP, lane, accf);

    const float4 gv = reinterpret_cast<const float4*>(ln_g)[lane];
    const float4 bv = reinterpret_cast<const float4*>(ln_b)[lane];

#pragma unroll
    for (int r = 0; r < ROWS_PER_WARP; ++r) {
        size_t row = rowBase + warp * ROWS_PER_WARP + r;
        float4 t2 = reinterpret_cast<const float4*>(g_tproj2 + row * DD)[lane];

        float z0 = silu_f(accf[r][0] + t2.x);
        float z1 = silu_f(accf[r][1] + t2.y);
        float z2 = silu_f(accf[r][2] + t2.z);
        float z3 = silu_f(accf[r][3] + t2.w);

        float mean, rstd;
        warp_ln_stats(z0, z1, z2, z3, mean, rstd);

        float4 d;
        d.x = (z0 - mean) * rstd * gv.x + bv.x;
        d.y = (z1 - mean) * rstd * gv.y + bv.y;
        d.z = (z2 - mean) * rstd * gv.z + bv.z;
        d.w = (z3 - mean) * rstd * gv.w + bv.w;

        float4 tin = reinterpret_cast<const float4*>(tgt + row * DD)[lane];
        float4 ov = make_float4(tin.x + d.x, tin.y + d.y, tin.z + d.z, tin.w + d.w);
        reinterpret_cast<float4*>(out_tgt + row * DD)[lane] = ov;
    }
}

// ==================== launch =================================================
extern "C" void kernel_launch(void* const* d_in, const int* in_sizes, int n_in,
                              void* d_out, int out_size) {
    const float* bond   = (const float*)d_in[0];
    const float* src    = (const float*)d_in[1];
    const float* tgt    = (const float*)d_in[2];
    const float* W_s2e  = (const float*)d_in[3];
    const float* W_t2e  = (const float*)d_in[4];
    const float* W_e2e  = (const float*)d_in[5];
    const float* ln1_g  = (const float*)d_in[6];
    const float* ln1_b  = (const float*)d_in[7];
    const float* W_e2t  = (const float*)d_in[8];
    const float* W_t2t  = (const float*)d_in[9];
    const float* ln2_g  = (const float*)d_in[10];
    const float* ln2_b  = (const float*)d_in[11];
    const float* coef   = (const float*)d_in[12];
    const int*   so     = (const int*)d_in[13];
    const int*   to     = (const int*)d_in[14];
    const int*   eo     = (const int*)d_in[15];

    float* out = (float*)d_out;
    float* out_bond = out;
    float* out_src  = out + (size_t)NB * NE * DD;
    float* out_tgt  = out_src + (size_t)NB * NSRC * DD;

    cudaFuncSetAttribute(k_gemm_mma, cudaFuncAttributeMaxDynamicSharedMemorySize, SM_TOTAL);
    cudaFuncSetAttribute(k_bond_mma, cudaFuncAttributeMaxDynamicSharedMemorySize, B_SM_TOT);
    const size_t smemN = SMEM_FLOATS * sizeof(float);
    cudaFuncSetAttribute(k_node, cudaFuncAttributeMaxDynamicSharedMemorySize, (int)smemN);

    float *sproj, *tproj, *tproj2;
    cudaGetSymbolAddress((void**)&sproj,  g_sproj);
    cudaGetSymbolAddress((void**)&tproj,  g_tproj);
    cudaGetSymbolAddress((void**)&tproj2, g_tproj2);

    cudaMemcpyAsync(out_src, src, (size_t)NB * NSRC * DD * sizeof(float),
                    cudaMemcpyDeviceToDevice);

    const int rowsNode = NB * NTGT;                       // 40000
    const int rowsBond = NB * NE;                         // 640000
    const int gridNode = (rowsNode + TM - 1) / TM;        // 313

    k_prep<<<64, 256>>>(W_e2e);

    k_gemm_mma<<<gridNode, 256, SM_TOTAL>>>(src, W_s2e, sproj,  rowsNode);
    k_gemm_mma<<<gridNode, 256, SM_TOTAL>>>(tgt, W_t2e, tproj,  rowsNode);
    k_gemm_mma<<<gridNode, 256, SM_TOTAL>>>(tgt, W_t2t, tproj2, rowsNode);

    k_bond_mma<<<rowsBond / 256, 512, B_SM_TOT>>>(bond, so, to, ln1_g, ln1_b, out_bond);

    k_node<<<rowsNode / ROWS_PER_BLK, 256, smemN>>>(tgt, W_e2t, coef, eo,
                                                    ln2_g, ln2_b, out_tgt);
}

// round 16
// speedup vs baseline: 1.4680x; 1.0643x over previous
#include <cuda_runtime.h>
#include <cuda_bf16.h>
#include <cstdint>
#include <cstddef>

// Problem constants
#define DD   128
#define NB   4
#define NSRC 10000
#define NTGT 10000
#define NE   160000
#define NK   16

// Scratch (device globals: allocation-free rule)
__device__ float g_sproj [NB * NSRC * DD];
__device__ float g_tproj [NB * NTGT * DD];
__device__ float g_tproj2[NB * NTGT * DD];
__device__ float g_dbond [NB * NE * DD];

typedef unsigned long long u64;
typedef unsigned int       u32;
typedef unsigned short     u16;

#define AH_STRIDE 136                    // bf16 elems per row (272B, conflict-free ldmatrix)
#define ROWB      (AH_STRIDE * 2)        // 272 bytes per tile row
#define WTILE_B   (DD * AH_STRIDE * 2)   // 34816 bytes: one 128x128 padded bf16 tile

// Precomputed W_e2e^T hi/lo tile images (exact smem layout, 16B aligned)
__device__ uint4 g_whT[WTILE_B / 16];
__device__ uint4 g_wlT[WTILE_B / 16];

static __device__ __forceinline__ u32 smem_u32(const void* p) {
    u32 a;
    asm("{ .reg .u64 t; cvta.to.shared.u64 t, %1; cvt.u32.u64 %0, t; }" : "=r"(a) : "l"(p));
    return a;
}

static __device__ __forceinline__ void ldmatrix_x4(u32* r, u32 addr) {
    asm volatile("ldmatrix.sync.aligned.m8n8.x4.shared.b16 {%0,%1,%2,%3}, [%4];"
                 : "=r"(r[0]), "=r"(r[1]), "=r"(r[2]), "=r"(r[3]) : "r"(addr));
}

static __device__ __forceinline__ void mma_bf16(float* c, const u32* a, u32 b0, u32 b1) {
    asm volatile("mma.sync.aligned.m16n8k16.row.col.f32.bf16.bf16.f32 "
                 "{%0,%1,%2,%3}, {%4,%5,%6,%7}, {%8,%9}, {%0,%1,%2,%3};"
                 : "+f"(c[0]), "+f"(c[1]), "+f"(c[2]), "+f"(c[3])
                 : "r"(a[0]), "r"(a[1]), "r"(a[2]), "r"(a[3]), "r"(b0), "r"(b1));
}

static __device__ __forceinline__ void split_bf16(float x, u16& h, u16& l) {
    __nv_bfloat16 hb = __float2bfloat16_rn(x);
    float xh = __bfloat162float(hb);
    __nv_bfloat16 lb = __float2bfloat16_rn(x - xh);
    h = __bfloat16_as_ushort(hb);
    l = __bfloat16_as_ushort(lb);
}

// Split a float2 into packed-hi (b32) and packed-lo (b32) bf16 pairs.
static __device__ __forceinline__ void split2_pack(float2 v, u32& hp, u32& lp) {
    u16 h0, l0, h1, l1;
    split_bf16(v.x, h0, l0);
    split_bf16(v.y, h1, l1);
    hp = (u32)h0 | ((u32)h1 << 16);
    lp = (u32)l0 | ((u32)l1 << 16);
}

static __device__ __forceinline__ float silu_f(float x) {
    return x / (1.0f + __expf(-x));
}

// ==================== k_prep: W_e2e -> transposed hi/lo tile images ==========
extern "C" __global__ void k_prep(const float* __restrict__ W) {
    int idx = blockIdx.x * 256 + threadIdx.x;        // 16384 total
    int k = idx >> 7, n = idx & 127;
    float x = W[k * DD + n];
    u16 h, l;
    split_bf16(x, h, l);
    u32 off = (u32)((n * AH_STRIDE + k) * 2);
    *(u16*)((char*)g_whT + off) = h;
    *(u16*)((char*)g_wlT + off) = l;
}

// ==================== k_bond_mma: 128 rows/CTA, 256 threads, occ 2 ===========
// smem: only W^T hi/lo tile images (69632 B) -> 2 CTAs/SM
#define BW_WH   0
#define BW_WL   34816
#define BW_TOT  69632

static __device__ __forceinline__ void warpquad_ln(float s, float q,
                                                   float& mean, float& rstd) {
    s += __shfl_xor_sync(0xffffffffu, s, 1);
    s += __shfl_xor_sync(0xffffffffu, s, 2);
    q += __shfl_xor_sync(0xffffffffu, q, 1);
    q += __shfl_xor_sync(0xffffffffu, q, 2);
    mean = s * (1.0f / DD);
    float var = q * (1.0f / DD) - mean * mean;
    rstd = rsqrtf(var + 1e-5f);
}

extern "C" __global__ void __launch_bounds__(256, 2)
k_bond_mma(const float* __restrict__ bond,
           const int* __restrict__ src_order, const int* __restrict__ tgt_order,
           const float* __restrict__ ln_g, const float* __restrict__ ln_b,
           float* __restrict__ out_bond) {
    extern __shared__ char sm[];
    u32 smb = smem_u32(sm);
    const int tid = threadIdx.x, lane = tid & 31, warp = tid >> 5;   // 8 warps
    const size_t rowBase = (size_t)blockIdx.x * 128;                 // 160000%128==0 -> batch-aligned

    // ---- prologue: copy precomputed W^T hi/lo images into smem ----
    {
        uint4* wh = (uint4*)(sm + BW_WH);
        uint4* wl = (uint4*)(sm + BW_WL);
#pragma unroll
        for (int i = 0; i < 9; ++i) {
            int f = tid + i * 256;
            if (f < WTILE_B / 16) {
                wh[f] = g_whT[f];
                wl[f] = g_wlT[f];
            }
        }
    }
    __syncthreads();

    // ---- mainloop: warp owns rows 16*warp .. 16*warp+15, all 128 cols ----
    // A fragments built in registers directly from gmem (no smem A tile).
    float C[16][4];
#pragma unroll
    for (int n = 0; n < 16; ++n)
#pragma unroll
        for (int j = 0; j < 4; ++j) C[n][j] = 0.f;

    const int g  = lane >> 2;
    const int c2 = (lane & 3) * 2;
    const int lrow0 = 16 * warp + g;        // rows this thread's a0/a2 touch
    const int lrow1 = lrow0 + 8;            // rows for a1/a3
    const float* arow0 = bond + (rowBase + lrow0) * DD;
    const float* arow1 = bond + (rowBase + lrow1) * DD;

    const int mat = lane >> 3;
    const int bn  = ((mat >> 1) << 3) + (lane & 7);
    const int bk  = (mat & 1) << 3;
    const u32 bH = smb + BW_WH + (u32)((bn * AH_STRIDE + bk) * 2);
    const u32 bL = bH + (BW_WL - BW_WH);

#pragma unroll
    for (int ks = 0; ks < 8; ++ks) {
        const int k0 = ks * 16;
        // A fragments: a0=A[g][k0+c2..], a1=A[g+8][k0+c2..], a2=A[g][k0+8+c2..], a3=A[g+8][k0+8+c2..]
        float2 v0 = *(const float2*)(arow0 + k0 + c2);
        float2 v1 = *(const float2*)(arow1 + k0 + c2);
        float2 v2 = *(const float2*)(arow0 + k0 + 8 + c2);
        float2 v3 = *(const float2*)(arow1 + k0 + 8 + c2);
        u32 ah[4], al[4];
        split2_pack(v0, ah[0], al[0]);
        split2_pack(v1, ah[1], al[1]);
        split2_pack(v2, ah[2], al[2]);
        split2_pack(v3, ah[3], al[3]);

        const u32 kb = (u32)(k0 * 2);
#pragma unroll
        for (int q = 0; q < 8; ++q) {
            u32 b4[4];
            ldmatrix_x4(b4, bH + (u32)(q * 16 * ROWB) + kb);
            mma_bf16(C[2 * q],     ah, b4[0], b4[1]);
            mma_bf16(C[2 * q + 1], ah, b4[2], b4[3]);
            mma_bf16(C[2 * q],     al, b4[0], b4[1]);
            mma_bf16(C[2 * q + 1], al, b4[2], b4[3]);
            u32 c4r[4];
            ldmatrix_x4(c4r, bL + (u32)(q * 16 * ROWB) + kb);
            mma_bf16(C[2 * q],     ah, c4r[0], c4r[1]);
            mma_bf16(C[2 * q + 1], ah, c4r[2], c4r[3]);
        }
    }

    // ---- epilogue: direct from fragments; LN per row within a lane-quad ----
    const size_t grow0 = rowBase + lrow0;
    const size_t grow1 = rowBase + lrow1;
    const int b = (int)(rowBase / NE);
    const int e0 = (int)(grow0 - (size_t)b * NE);
    const int e1 = (int)(grow1 - (size_t)b * NE);
    const int so0 = __ldg(src_order + e0), to0 = __ldg(tgt_order + e0);
    const int so1 = __ldg(src_order + e1), to1 = __ldg(tgt_order + e1);
    const float* sp0 = g_sproj + ((size_t)b * NSRC + so0) * DD;
    const float* tp0 = g_tproj + ((size_t)b * NTGT + to0) * DD;
    const float* sp1 = g_sproj + ((size_t)b * NSRC + so1) * DD;
    const float* tp1 = g_tproj + ((size_t)b * NTGT + to1) * DD;

    float s0 = 0.f, q0 = 0.f, s1 = 0.f, q1 = 0.f;
#pragma unroll
    for (int n = 0; n < 16; ++n) {
        int col = n * 8 + c2;
        float2 a0 = *(const float2*)(sp0 + col);
        float2 b0 = *(const float2*)(tp0 + col);
        float2 a1 = *(const float2*)(sp1 + col);
        float2 b1 = *(const float2*)(tp1 + col);
        float z;
        z = silu_f(C[n][0] + a0.x + b0.x); C[n][0] = z; s0 += z; q0 += z * z;
        z = silu_f(C[n][1] + a0.y + b0.y); C[n][1] = z; s0 += z; q0 += z * z;
        z = silu_f(C[n][2] + a1.x + b1.x); C[n][2] = z; s1 += z; q1 += z * z;
        z = silu_f(C[n][3] + a1.y + b1.y); C[n][3] = z; s1 += z; q1 += z * z;
    }
    float m0, r0, m1, r1;
    warpquad_ln(s0, q0, m0, r0);
    warpquad_ln(s1, q1, m1, r1);

    float* db_out0 = g_dbond + grow0 * DD;
    float* db_out1 = g_dbond + grow1 * DD;
    float* ob0 = out_bond + grow0 * DD;
    float* ob1 = out_bond + grow1 * DD;

#pragma unroll
    for (int n = 0; n < 16; ++n) {
        int col = n * 8 + c2;
        float2 gg = *(const float2*)(ln_g + col);
        float2 bb = *(const float2*)(ln_b + col);
        float2 d0, d1;
        d0.x = (C[n][0] - m0) * r0 * gg.x + bb.x;
        d0.y = (C[n][1] - m0) * r0 * gg.y + bb.y;
        d1.x = (C[n][2] - m1) * r1 * gg.x + bb.x;
        d1.y = (C[n][3] - m1) * r1 * gg.y + bb.y;
        *(float2*)(db_out0 + col) = d0;
        *(float2*)(db_out1 + col) = d1;
        // exact residual: re-read bond (L1/L2-hot, fp32 exact)
        float2 x0 = *(const float2*)(arow0 + col);
        float2 x1 = *(const float2*)(arow1 + col);
        *(float2*)(ob0 + col) = make_float2(x0.x + d0.x, x0.y + d0.y);
        *(float2*)(ob1 + col) = make_float2(x1.x + d1.x, x1.y + d1.y);
    }
}

// ==================== small GEMMs: validated TM=128 HMMA path ================
#define TM 128
#define SM_AH   0
#define SM_AL   34816
#define SM_WH   69632
#define SM_WL   104448
#define SM_STG  139264
#define SM_TOTAL 206848
#define WSTG_STRIDE 129
#define DST_STRIDE  132

static __device__ __forceinline__ void mma_prologue(char* sm,
                                                    const float* __restrict__ Xrow0, int rowsValid,
                                                    const float* __restrict__ W,
                                                    int tid, int warp, int lane) {
    {
        const float4* Xf4 = (const float4*)Xrow0;
#pragma unroll
        for (int i = 0; i < 16; ++i) {
            int f = tid + i * 256;
            int r = f >> 5, c4 = (f & 31) << 2;
            int rr = (r < rowsValid) ? r : (rowsValid - 1);
            float4 v = Xf4[rr * 32 + (f & 31)];
            u16 h0, l0, h1, l1, h2, l2, h3, l3;
            split_bf16(v.x, h0, l0); split_bf16(v.y, h1, l1);
            split_bf16(v.z, h2, l2); split_bf16(v.w, h3, l3);
            u64 hp = (u64)h0 | ((u64)h1 << 16) | ((u64)h2 << 32) | ((u64)h3 << 48);
            u64 lp = (u64)l0 | ((u64)l1 << 16) | ((u64)l2 << 32) | ((u64)l3 << 48);
            u32 off = (u32)((r * AH_STRIDE + c4) * 2);
            *(u64*)(sm + SM_AH + off) = hp;
            *(u64*)(sm + SM_AL + off) = lp;
        }
    }
    {
        float* Wstg = (float*)(sm + SM_STG);
        const float4* Wf4 = (const float4*)W;
#pragma unroll
        for (int i = 0; i < 16; ++i) {
            int f = tid + i * 256;
            int k = f >> 5, n4 = (f & 31) << 2;
            float4 v = Wf4[f];
            Wstg[k * WSTG_STRIDE + n4 + 0] = v.x;
            Wstg[k * WSTG_STRIDE + n4 + 1] = v.y;
            Wstg[k * WSTG_STRIDE + n4 + 2] = v.z;
            Wstg[k * WSTG_STRIDE + n4 + 3] = v.w;
        }
    }
    __syncthreads();
    {
        const float* Wstg = (const float*)(sm + SM_STG);
#pragma unroll
        for (int i = 0; i < 16; ++i) {
            int n = warp * 16 + i;
#pragma unroll
            for (int j = 0; j < 4; ++j) {
                int k = lane + 32 * j;
                float x = Wstg[k * WSTG_STRIDE + n];
                u16 h, l;
                split_bf16(x, h, l);
                u32 off = (u32)((n * AH_STRIDE + k) * 2);
                *(u16*)(sm + SM_WH + off) = h;
                *(u16*)(sm + SM_WL + off) = l;
            }
        }
    }
    __syncthreads();
}

static __device__ __forceinline__ void mma_main128(u32 smb, int warp, int lane,
                                                   float C[2][8][4]) {
#pragma unroll
    for (int m = 0; m < 2; ++m)
#pragma unroll
        for (int n = 0; n < 8; ++n)
#pragma unroll
            for (int j = 0; j < 4; ++j) C[m][n][j] = 0.f;

    const int rowbase = (warp & 3) * 32;
    const int colbase = (warp >> 2) * 64;
    const int ar = lane & 15;
    const int ac = (lane >> 4) << 3;
    const u32 aoffH = smb + SM_AH + (u32)(((rowbase + ar) * AH_STRIDE + ac) * 2);
    const u32 aoffL = aoffH + (SM_AL - SM_AH);
    const int mat = lane >> 3;
    const int bn  = colbase + ((mat >> 1) << 3) + (lane & 7);
    const int bk  = (mat & 1) << 3;
    const u32 boffH = smb + SM_WH + (u32)((bn * AH_STRIDE + bk) * 2);
    const u32 boffL = boffH + (SM_WL - SM_WH);

#pragma unroll
    for (int ks = 0; ks < 8; ++ks) {
        const u32 kb = (u32)(ks * 32);
        u32 ah[2][4], al[2][4], b[4][4];
        ldmatrix_x4(ah[0], aoffH + kb);
        ldmatrix_x4(ah[1], aoffH + 16 * ROWB + kb);
        ldmatrix_x4(al[0], aoffL + kb);
        ldmatrix_x4(al[1], aoffL + 16 * ROWB + kb);
#pragma unroll
        for (int q = 0; q < 4; ++q) ldmatrix_x4(b[q], boffH + (u32)(q * 16 * ROWB) + kb);
#pragma unroll
        for (int m = 0; m < 2; ++m)
#pragma unroll
            for (int n = 0; n < 8; ++n)
                mma_bf16(C[m][n], ah[m], b[n >> 1][(n & 1) * 2], b[n >> 1][(n & 1) * 2 + 1]);
#pragma unroll
        for (int m = 0; m < 2; ++m)
#pragma unroll
            for (int n = 0; n < 8; ++n)
                mma_bf16(C[m][n], al[m], b[n >> 1][(n & 1) * 2], b[n >> 1][(n & 1) * 2 + 1]);
#pragma unroll
        for (int q = 0; q < 4; ++q) ldmatrix_x4(b[q], boffL + (u32)(q * 16 * ROWB) + kb);
#pragma unroll
        for (int m = 0; m < 2; ++m)
#pragma unroll
            for (int n = 0; n < 8; ++n)
                mma_bf16(C[m][n], ah[m], b[n >> 1][(n & 1) * 2], b[n >> 1][(n & 1) * 2 + 1]);
    }
}

extern "C" __global__ void __launch_bounds__(256, 1)
k_gemm_mma(const float* __restrict__ X, const float* __restrict__ W,
           float* __restrict__ Y, int totalRows) {
    extern __shared__ char sm[];
    u32 smb = smem_u32(sm);
    const int tid = threadIdx.x, lane = tid & 31, warp = tid >> 5;
    const size_t rowBase = (size_t)blockIdx.x * TM;
    int rowsValid = totalRows - (int)rowBase;
    if (rowsValid > TM) rowsValid = TM;

    mma_prologue(sm, X + rowBase * DD, rowsValid, W, tid, warp, lane);

    float C[2][8][4];
    mma_main128(smb, warp, lane, C);

    {
        float* Ds = (float*)(sm + SM_STG);
        const int rowbase = (warp & 3) * 32;
        const int colbase = (warp >> 2) * 64;
        const int g  = lane >> 2;
        const int tq = lane & 3;
        __syncthreads();
#pragma unroll
        for (int m = 0; m < 2; ++m) {
            int r0 = rowbase + m * 16 + g;
#pragma unroll
            for (int n = 0; n < 8; ++n) {
                int col = colbase + n * 8 + tq * 2;
                *(float2*)&Ds[r0 * DST_STRIDE + col]       = make_float2(C[m][n][0], C[m][n][1]);
                *(float2*)&Ds[(r0 + 8) * DST_STRIDE + col] = make_float2(C[m][n][2], C[m][n][3]);
            }
        }
        __syncthreads();
    }
    const float* Ds = (const float*)(sm + SM_STG);
#pragma unroll 4
    for (int rr = 0; rr < 16; ++rr) {
        int r = warp * 16 + rr;
        if (r < rowsValid) {
            size_t row = rowBase + r;
            float4 v = *(const float4*)&Ds[r * DST_STRIDE + lane * 4];
            reinterpret_cast<float4*>(Y + row * DD)[lane] = v;
        }
    }
}

// ==================== Kernel 3: node update (FFMA2 scalar path) ==============
#define ROWS_PER_WARP 8
#define ROWS_PER_BLK  64
#define XT_STRIDE     66
#define SMEM_FLOATS   (DD * DD + DD * XT_STRIDE)

static __device__ __forceinline__ u64 dup_f32x2(float w) {
    u64 r; asm("mov.b64 %0, {%1, %1};" : "=l"(r) : "f"(w)); return r;
}
static __device__ __forceinline__ u64 ffma2(u64 a, u64 b, u64 c) {
    u64 d; asm("fma.rn.f32x2 %0, %1, %2, %3;" : "=l"(d) : "l"(a), "l"(b), "l"(c)); return d;
}
static __device__ __forceinline__ void unpack2(u64 v, float& lo, float& hi) {
    asm("mov.b64 {%0, %1}, %2;" : "=f"(lo), "=f"(hi) : "l"(v));
}
static __device__ __forceinline__ void load_w_smem(float* Ws, const float* __restrict__ W, int tid) {
    const float4* src = reinterpret_cast<const float4*>(W);
    float4* dst = reinterpret_cast<float4*>(Ws);
#pragma unroll
    for (int i = 0; i < 16; ++i) dst[tid + i * 256] = src[tid + i * 256];
}
static __device__ __forceinline__ void gemm_tile2(const float* __restrict__ Ws,
                                                  const float* __restrict__ XsT,
                                                  int wrow0, int lane,
                                                  float accf[ROWS_PER_WARP][4]) {
    u64 acc2[4][4];
#pragma unroll
    for (int p = 0; p < 4; ++p)
#pragma unroll
        for (int c = 0; c < 4; ++c) acc2[p][c] = 0ull;
#pragma unroll 4
    for (int k = 0; k < DD; ++k) {
        float4 wv = reinterpret_cast<const float4*>(Ws + k * DD)[lane];
        u64 w0 = dup_f32x2(wv.x), w1 = dup_f32x2(wv.y);
        u64 w2 = dup_f32x2(wv.z), w3 = dup_f32x2(wv.w);
        const float* xb = XsT + k * XT_STRIDE + wrow0;
#pragma unroll
        for (int p = 0; p < 4; ++p) {
            u64 xp = *reinterpret_cast<const u64*>(xb + 2 * p);
            acc2[p][0] = ffma2(xp, w0, acc2[p][0]);
            acc2[p][1] = ffma2(xp, w1, acc2[p][1]);
            acc2[p][2] = ffma2(xp, w2, acc2[p][2]);
            acc2[p][3] = ffma2(xp, w3, acc2[p][3]);
        }
    }
#pragma unroll
    for (int p = 0; p < 4; ++p)
#pragma unroll
        for (int c = 0; c < 4; ++c)
            unpack2(acc2[p][c], accf[2 * p][c], accf[2 * p + 1][c]);
}

static __device__ __forceinline__ void warp_ln_stats(float z0, float z1, float z2, float z3,
                                                     float& mean, float& rstd) {
    float s  = z0 + z1 + z2 + z3;
    float s2 = z0 * z0 + z1 * z1 + z2 * z2 + z3 * z3;
#pragma unroll
    for (int off = 16; off; off >>= 1) {
        s  += __shfl_xor_sync(0xffffffffu, s,  off);
        s2 += __shfl_xor_sync(0xffffffffu, s2, off);
    }
    mean = s * (1.0f / DD);
    float var = s2 * (1.0f / DD) - mean * mean;
    rstd = rsqrtf(var + 1e-5f);
}

extern "C" __global__ void __launch_bounds__(256, 2)
k_node(const float* __restrict__ tgt, const float* __restrict__ W,
       const float* __restrict__ coef, const int* __restrict__ edge_order,
       const float* __restrict__ ln_g, const float* __restrict__ ln_b,
       float* __restrict__ out_tgt) {
    extern __shared__ float smf[];
    float* Ws  = smf;
    float* XsT = smf + DD * DD;
    const int tid = threadIdx.x, lane = tid & 31, warp = tid >> 5;
    const size_t rowBase = (size_t)blockIdx.x * ROWS_PER_BLK;

    load_w_smem(Ws, W, tid);

#pragma unroll
    for (int r = 0; r < ROWS_PER_WARP; ++r) {
        int rl = warp * ROWS_PER_WARP + r;
        size_t row = rowBase + rl;
        int b = (int)(row / NTGT);
        int t = (int)(row - (size_t)b * NTGT);
        float4 acc4 = make_float4(0.f, 0.f, 0.f, 0.f);
#pragma unroll
        for (int k = 0; k < NK; ++k) {
            int e   = __ldg(edge_order + (size_t)t * NK + k);
            float c = __ldg(coef       + (size_t)t * NK + k);
            float4 v = reinterpret_cast<const float4*>(g_dbond + ((size_t)b * NE + e) * DD)[lane];
            acc4.x += c * v.x; acc4.y += c * v.y;
            acc4.z += c * v.z; acc4.w += c * v.w;
        }
        const float inv_k = 1.0f / NK;
        int k0 = lane * 4;
        XsT[(k0 + 0) * XT_STRIDE + rl] = acc4.x * inv_k;
        XsT[(k0 + 1) * XT_STRIDE + rl] = acc4.y * inv_k;
        XsT[(k0 + 2) * XT_STRIDE + rl] = acc4.z * inv_k;
        XsT[(k0 + 3) * XT_STRIDE + rl] = acc4.w * inv_k;
    }
    __syncthreads();

    float accf[ROWS_PER_WARP][4];
    gemm_tile2(Ws, XsT, warp * ROWS_PER_WARP, lane, accf);

    const float4 gv = reinterpret_cast<const float4*>(ln_g)[lane];
    const float4 bv = reinterpret_cast<const float4*>(ln_b)[lane];

#pragma unroll
    for (int r = 0; r < ROWS_PER_WARP; ++r) {
        size_t row = rowBase + warp * ROWS_PER_WARP + r;
        float4 t2 = reinterpret_cast<const float4*>(g_tproj2 + row * DD)[lane];

        float z0 = silu_f(accf[r][0] + t2.x);
        float z1 = silu_f(accf[r][1] + t2.y);
        float z2 = silu_f(accf[r][2] + t2.z);
        float z3 = silu_f(accf[r][3] + t2.w);

        float mean, rstd;
        warp_ln_stats(z0, z1, z2, z3, mean, rstd);

        float4 d;
        d.x = (z0 - mean) * rstd * gv.x + bv.x;
        d.y = (z1 - mean) * rstd * gv.y + bv.y;
        d.z = (z2 - mean) * rstd * gv.z + bv.z;
        d.w = (z3 - mean) * rstd * gv.w + bv.w;

        float4 tin = reinterpret_cast<const float4*>(tgt + row * DD)[lane];
        float4 ov = make_float4(tin.x + d.x, tin.y + d.y, tin.z + d.z, tin.w + d.w);
        reinterpret_cast<float4*>(out_tgt + row * DD)[lane] = ov;
    }
}

// ==================== launch =================================================
extern "C" void kernel_launch(void* const* d_in, const int* in_sizes, int n_in,
                              void* d_out, int out_size) {
    const float* bond   = (const float*)d_in[0];
    const float* src    = (const float*)d_in[1];
    const float* tgt    = (const float*)d_in[2];
    const float* W_s2e  = (const float*)d_in[3];
    const float* W_t2e  = (const float*)d_in[4];
    const float* W_e2e  = (const float*)d_in[5];
    const float* ln1_g  = (const float*)d_in[6];
    const float* ln1_b  = (const float*)d_in[7];
    const float* W_e2t  = (const float*)d_in[8];
    const float* W_t2t  = (const float*)d_in[9];
    const float* ln2_g  = (const float*)d_in[10];
    const float* ln2_b  = (const float*)d_in[11];
    const float* coef   = (const float*)d_in[12];
    const int*   so     = (const int*)d_in[13];
    const int*   to     = (const int*)d_in[14];
    const int*   eo     = (const int*)d_in[15];

    float* out = (float*)d_out;
    float* out_bond = out;
    float* out_src  = out + (size_t)NB * NE * DD;
    float* out_tgt  = out_src + (size_t)NB * NSRC * DD;

    cudaFuncSetAttribute(k_gemm_mma, cudaFuncAttributeMaxDynamicSharedMemorySize, SM_TOTAL);
    cudaFuncSetAttribute(k_bond_mma, cudaFuncAttributeMaxDynamicSharedMemorySize, BW_TOT);
    const size_t smemN = SMEM_FLOATS * sizeof(float);
    cudaFuncSetAttribute(k_node, cudaFuncAttributeMaxDynamicSharedMemorySize, (int)smemN);

    float *sproj, *tproj, *tproj2;
    cudaGetSymbolAddress((void**)&sproj,  g_sproj);
    cudaGetSymbolAddress((void**)&tproj,  g_tproj);
    cudaGetSymbolAddress((void**)&tproj2, g_tproj2);

    cudaMemcpyAsync(out_src, src, (size_t)NB * NSRC * DD * sizeof(float),
                    cudaMemcpyDeviceToDevice);

    const int rowsNode = NB * NTGT;                       // 40000
    const int rowsBond = NB * NE;                         // 640000
    const int gridNode = (rowsNode + TM - 1) / TM;        // 313

    k_prep<<<64, 256>>>(W_e2e);

    k_gemm_mma<<<gridNode, 256, SM_TOTAL>>>(src, W_s2e, sproj,  rowsNode);
    k_gemm_mma<<<gridNode, 256, SM_TOTAL>>>(tgt, W_t2e, tproj,  rowsNode);
    k_gemm_mma<<<gridNode, 256, SM_TOTAL>>>(tgt, W_t2t, tproj2, rowsNode);

    k_bond_mma<<<rowsBond / 128, 256, BW_TOT>>>(bond, so, to, ln1_g, ln1_b, out_bond);

    k_node<<<rowsNode / ROWS_PER_BLK, 256, smemN>>>(tgt, W_e2t, coef, eo,
                                                    ln2_g, ln2_b, out_tgt);
}

// round 17
// speedup vs baseline: 1.6271x; 1.1083x over previous
#include <cuda_runtime.h>
#include <cuda_bf16.h>
#include <cstdint>
#include <cstddef>

// Problem constants
#define DD   128
#define NB   4
#define NSRC 10000
#define NTGT 10000
#define NE   160000
#define NK   16

// Scratch (device globals: allocation-free rule)
__device__ float g_sproj [NB * NSRC * DD];
__device__ float g_tproj [NB * NTGT * DD];
__device__ float g_tproj2[NB * NTGT * DD];
__device__ float g_dbond [NB * NE * DD];

typedef unsigned long long u64;
typedef unsigned int       u32;
typedef unsigned short     u16;

#define AH_STRIDE 136                    // bf16 elems per row (272B, conflict-free ldmatrix)
#define ROWB      (AH_STRIDE * 2)        // 272 bytes per tile row
#define WTILE_B   (DD * AH_STRIDE * 2)   // 34816 bytes: one 128x128 padded bf16 tile

// Precomputed W^T hi/lo tile images for all 4 weights:
// 0: W_s2e, 1: W_t2e, 2: W_t2t, 3: W_e2e
__device__ uint4 g_whT4[4][WTILE_B / 16];
__device__ uint4 g_wlT4[4][WTILE_B / 16];

static __device__ __forceinline__ u32 smem_u32(const void* p) {
    u32 a;
    asm("{ .reg .u64 t; cvta.to.shared.u64 t, %1; cvt.u32.u64 %0, t; }" : "=r"(a) : "l"(p));
    return a;
}

static __device__ __forceinline__ void ldmatrix_x4(u32* r, u32 addr) {
    asm volatile("ldmatrix.sync.aligned.m8n8.x4.shared.b16 {%0,%1,%2,%3}, [%4];"
                 : "=r"(r[0]), "=r"(r[1]), "=r"(r[2]), "=r"(r[3]) : "r"(addr));
}

static __device__ __forceinline__ void mma_bf16(float* c, const u32* a, u32 b0, u32 b1) {
    asm volatile("mma.sync.aligned.m16n8k16.row.col.f32.bf16.bf16.f32 "
                 "{%0,%1,%2,%3}, {%4,%5,%6,%7}, {%8,%9}, {%0,%1,%2,%3};"
                 : "+f"(c[0]), "+f"(c[1]), "+f"(c[2]), "+f"(c[3])
                 : "r"(a[0]), "r"(a[1]), "r"(a[2]), "r"(a[3]), "r"(b0), "r"(b1));
}

static __device__ __forceinline__ void split_bf16(float x, u16& h, u16& l) {
    __nv_bfloat16 hb = __float2bfloat16_rn(x);
    float xh = __bfloat162float(hb);
    __nv_bfloat16 lb = __float2bfloat16_rn(x - xh);
    h = __bfloat16_as_ushort(hb);
    l = __bfloat16_as_ushort(lb);
}

// Fast split: packed cvt + shift-trick.  hp = {bf16(v.y), bf16(v.x)}, lp = residual pair.
static __device__ __forceinline__ void split2_pack(float2 v, u32& hp, u32& lp) {
    asm("cvt.rn.bf16x2.f32 %0, %1, %2;" : "=r"(hp) : "f"(v.y), "f"(v.x));
    float xh0 = __uint_as_float(hp << 16);
    float xh1 = __uint_as_float(hp & 0xffff0000u);
    float l0 = v.x - xh0;
    float l1 = v.y - xh1;
    asm("cvt.rn.bf16x2.f32 %0, %1, %2;" : "=r"(lp) : "f"(l1), "f"(l0));
}

static __device__ __forceinline__ float silu_f(float x) {
    return x / (1.0f + __expf(-x));
}

static __device__ __forceinline__ void warpquad_ln(float s, float q,
                                                   float& mean, float& rstd) {
    s += __shfl_xor_sync(0xffffffffu, s, 1);
    s += __shfl_xor_sync(0xffffffffu, s, 2);
    q += __shfl_xor_sync(0xffffffffu, q, 1);
    q += __shfl_xor_sync(0xffffffffu, q, 2);
    mean = s * (1.0f / DD);
    float var = q * (1.0f / DD) - mean * mean;
    rstd = rsqrtf(var + 1e-5f);
}

// ==================== k_prep: 4 weights -> transposed hi/lo tile images ======
extern "C" __global__ void k_prep(const float* __restrict__ W0, const float* __restrict__ W1,
                                  const float* __restrict__ W2, const float* __restrict__ W3) {
    int idx = blockIdx.x * 256 + threadIdx.x;        // 4*16384 total
    int w = idx >> 14, r = idx & 16383;
    const float* W = (w == 0) ? W0 : (w == 1) ? W1 : (w == 2) ? W2 : W3;
    int k = r >> 7, n = r & 127;
    float x = W[k * DD + n];
    u16 h, l;
    split_bf16(x, h, l);
    u32 off = (u32)((n * AH_STRIDE + k) * 2);
    *(u16*)((char*)g_whT4[w] + off) = h;
    *(u16*)((char*)g_wlT4[w] + off) = l;
}

// smem: W^T hi/lo tile images only (69632 B) -> 2 CTAs/SM
#define BW_WH   0
#define BW_WL   34816
#define BW_TOT  69632

// ==================== shared mainloop core ===================================
// warp = 16 rows x 128 cols; A fragments from gmem; W from smem images.
// arow0/arow1 must point at valid rows (clamped by caller).
static __device__ __forceinline__ void bond_mainloop(u32 smb, int lane,
                                                     const float* __restrict__ arow0,
                                                     const float* __restrict__ arow1,
                                                     float C[16][4]) {
#pragma unroll
    for (int n = 0; n < 16; ++n)
#pragma unroll
        for (int j = 0; j < 4; ++j) C[n][j] = 0.f;

    const int c2 = (lane & 3) * 2;
    const int mat = lane >> 3;
    const int bn  = ((mat >> 1) << 3) + (lane & 7);
    const int bk  = (mat & 1) << 3;
    const u32 bH = smb + BW_WH + (u32)((bn * AH_STRIDE + bk) * 2);
    const u32 bL = bH + (BW_WL - BW_WH);

#pragma unroll
    for (int ks = 0; ks < 8; ++ks) {
        const int k0 = ks * 16;
        float2 v0 = *(const float2*)(arow0 + k0 + c2);
        float2 v1 = *(const float2*)(arow1 + k0 + c2);
        float2 v2 = *(const float2*)(arow0 + k0 + 8 + c2);
        float2 v3 = *(const float2*)(arow1 + k0 + 8 + c2);
        u32 ah[4], al[4];
        split2_pack(v0, ah[0], al[0]);
        split2_pack(v1, ah[1], al[1]);
        split2_pack(v2, ah[2], al[2]);
        split2_pack(v3, ah[3], al[3]);

        const u32 kb = (u32)(k0 * 2);
#pragma unroll
        for (int q = 0; q < 8; ++q) {
            u32 b4[4];
            ldmatrix_x4(b4, bH + (u32)(q * 16 * ROWB) + kb);
            mma_bf16(C[2 * q],     ah, b4[0], b4[1]);
            mma_bf16(C[2 * q + 1], ah, b4[2], b4[3]);
            mma_bf16(C[2 * q],     al, b4[0], b4[1]);
            mma_bf16(C[2 * q + 1], al, b4[2], b4[3]);
            u32 c4r[4];
            ldmatrix_x4(c4r, bL + (u32)(q * 16 * ROWB) + kb);
            mma_bf16(C[2 * q],     ah, c4r[0], c4r[1]);
            mma_bf16(C[2 * q + 1], ah, c4r[2], c4r[3]);
        }
    }
}

static __device__ __forceinline__ void copy_w_images(char* sm, int tid, int wsel) {
    uint4* wh = (uint4*)(sm + BW_WH);
    uint4* wl = (uint4*)(sm + BW_WL);
    const uint4* gh = g_whT4[wsel];
    const uint4* gl = g_wlT4[wsel];
#pragma unroll
    for (int i = 0; i < 9; ++i) {
        int f = tid + i * 256;
        if (f < WTILE_B / 16) {
            wh[f] = gh[f];
            wl[f] = gl[f];
        }
    }
}

// ==================== k_bond_mma: 128 rows/CTA, 256 threads, occ 2 ===========
extern "C" __global__ void __launch_bounds__(256, 2)
k_bond_mma(const float* __restrict__ bond,
           const int* __restrict__ src_order, const int* __restrict__ tgt_order,
           const float* __restrict__ ln_g, const float* __restrict__ ln_b,
           float* __restrict__ out_bond) {
    extern __shared__ char sm[];
    u32 smb = smem_u32(sm);
    const int tid = threadIdx.x, lane = tid & 31, warp = tid >> 5;   // 8 warps
    const size_t rowBase = (size_t)blockIdx.x * 128;

    copy_w_images(sm, tid, 3);
    __syncthreads();

    const int g  = lane >> 2;
    const int c2 = (lane & 3) * 2;
    const int lrow0 = 16 * warp + g;
    const int lrow1 = lrow0 + 8;
    const float* arow0 = bond + (rowBase + lrow0) * DD;
    const float* arow1 = bond + (rowBase + lrow1) * DD;

    float C[16][4];
    bond_mainloop(smb, lane, arow0, arow1, C);

    // ---- epilogue ----
    const size_t grow0 = rowBase + lrow0;
    const size_t grow1 = rowBase + lrow1;
    const int b = (int)(rowBase / NE);
    const int e0 = (int)(grow0 - (size_t)b * NE);
    const int e1 = (int)(grow1 - (size_t)b * NE);
    const int so0 = __ldg(src_order + e0), to0 = __ldg(tgt_order + e0);
    const int so1 = __ldg(src_order + e1), to1 = __ldg(tgt_order + e1);
    const float* sp0 = g_sproj + ((size_t)b * NSRC + so0) * DD;
    const float* tp0 = g_tproj + ((size_t)b * NTGT + to0) * DD;
    const float* sp1 = g_sproj + ((size_t)b * NSRC + so1) * DD;
    const float* tp1 = g_tproj + ((size_t)b * NTGT + to1) * DD;

    float s0 = 0.f, q0 = 0.f, s1 = 0.f, q1 = 0.f;
#pragma unroll
    for (int n = 0; n < 16; ++n) {
        int col = n * 8 + c2;
        float2 a0 = *(const float2*)(sp0 + col);
        float2 b0 = *(const float2*)(tp0 + col);
        float2 a1 = *(const float2*)(sp1 + col);
        float2 b1 = *(const float2*)(tp1 + col);
        float z;
        z = silu_f(C[n][0] + a0.x + b0.x); C[n][0] = z; s0 += z; q0 += z * z;
        z = silu_f(C[n][1] + a0.y + b0.y); C[n][1] = z; s0 += z; q0 += z * z;
        z = silu_f(C[n][2] + a1.x + b1.x); C[n][2] = z; s1 += z; q1 += z * z;
        z = silu_f(C[n][3] + a1.y + b1.y); C[n][3] = z; s1 += z; q1 += z * z;
    }
    float m0, r0, m1, r1;
    warpquad_ln(s0, q0, m0, r0);
    warpquad_ln(s1, q1, m1, r1);

    float* db_out0 = g_dbond + grow0 * DD;
    float* db_out1 = g_dbond + grow1 * DD;
    float* ob0 = out_bond + grow0 * DD;
    float* ob1 = out_bond + grow1 * DD;

#pragma unroll
    for (int n = 0; n < 16; ++n) {
        int col = n * 8 + c2;
        float2 gg = *(const float2*)(ln_g + col);
        float2 bb = *(const float2*)(ln_b + col);
        float2 d0, d1;
        d0.x = (C[n][0] - m0) * r0 * gg.x + bb.x;
        d0.y = (C[n][1] - m0) * r0 * gg.y + bb.y;
        d1.x = (C[n][2] - m1) * r1 * gg.x + bb.x;
        d1.y = (C[n][3] - m1) * r1 * gg.y + bb.y;
        *(float2*)(db_out0 + col) = d0;
        *(float2*)(db_out1 + col) = d1;
        float2 x0 = *(const float2*)(arow0 + col);
        float2 x1 = *(const float2*)(arow1 + col);
        *(float2*)(ob0 + col) = make_float2(x0.x + d0.x, x0.y + d0.y);
        *(float2*)(ob1 + col) = make_float2(x1.x + d1.x, x1.y + d1.y);
    }
}

// ==================== k_proj_mma: fused 3 projection GEMMs ===================
// grid = 3 * 313; wsel picks {src@W_s2e->sproj, tgt@W_t2e->tproj, tgt@W_t2t->tproj2}
#define NTILES 313
extern "C" __global__ void __launch_bounds__(256, 2)
k_proj_mma(const float* __restrict__ src, const float* __restrict__ tgt,
           float* __restrict__ Y0, float* __restrict__ Y1, float* __restrict__ Y2) {
    extern __shared__ char sm[];
    u32 smb = smem_u32(sm);
    const int tid = threadIdx.x, lane = tid & 31, warp = tid >> 5;
    const int wsel = blockIdx.x / NTILES;
    const int tile = blockIdx.x - wsel * NTILES;
    const float* X = (wsel == 0) ? src : tgt;
    float* Y = (wsel == 0) ? Y0 : (wsel == 1) ? Y1 : Y2;
    const int rowBase = tile * 128;
    const int rowsValid = min(128, NB * NTGT - rowBase);   // 40000 rows total

    copy_w_images(sm, tid, wsel);
    __syncthreads();

    const int g  = lane >> 2;
    const int c2 = (lane & 3) * 2;
    const int lrow0 = 16 * warp + g;
    const int lrow1 = lrow0 + 8;
    const int cl0 = (lrow0 < rowsValid) ? lrow0 : (rowsValid - 1);
    const int cl1 = (lrow1 < rowsValid) ? lrow1 : (rowsValid - 1);
    const float* arow0 = X + (size_t)(rowBase + cl0) * DD;
    const float* arow1 = X + (size_t)(rowBase + cl1) * DD;

    float C[16][4];
    bond_mainloop(smb, lane, arow0, arow1, C);

    // direct store
    float* y0 = Y + (size_t)(rowBase + lrow0) * DD;
    float* y1 = Y + (size_t)(rowBase + lrow1) * DD;
    const bool ok0 = (lrow0 < rowsValid);
    const bool ok1 = (lrow1 < rowsValid);
#pragma unroll
    for (int n = 0; n < 16; ++n) {
        int col = n * 8 + c2;
        if (ok0) *(float2*)(y0 + col) = make_float2(C[n][0], C[n][1]);
        if (ok1) *(float2*)(y1 + col) = make_float2(C[n][2], C[n][3]);
    }
}

// ==================== Kernel 3: node update (FFMA2 scalar path) ==============
#define ROWS_PER_WARP 8
#define ROWS_PER_BLK  64
#define XT_STRIDE     66
#define SMEM_FLOATS   (DD * DD + DD * XT_STRIDE)

static __device__ __forceinline__ u64 dup_f32x2(float w) {
    u64 r; asm("mov.b64 %0, {%1, %1};" : "=l"(r) : "f"(w)); return r;
}
static __device__ __forceinline__ u64 ffma2(u64 a, u64 b, u64 c) {
    u64 d; asm("fma.rn.f32x2 %0, %1, %2, %3;" : "=l"(d) : "l"(a), "l"(b), "l"(c)); return d;
}
static __device__ __forceinline__ void unpack2(u64 v, float& lo, float& hi) {
    asm("mov.b64 {%0, %1}, %2;" : "=f"(lo), "=f"(hi) : "l"(v));
}
static __device__ __forceinline__ void load_w_smem(float* Ws, const float* __restrict__ W, int tid) {
    const float4* src = reinterpret_cast<const float4*>(W);
    float4* dst = reinterpret_cast<float4*>(Ws);
#pragma unroll
    for (int i = 0; i < 16; ++i) dst[tid + i * 256] = src[tid + i * 256];
}
static __device__ __forceinline__ void gemm_tile2(const float* __restrict__ Ws,
                                                  const float* __restrict__ XsT,
                                                  int wrow0, int lane,
                                                  float accf[ROWS_PER_WARP][4]) {
    u64 acc2[4][4];
#pragma unroll
    for (int p = 0; p < 4; ++p)
#pragma unroll
        for (int c = 0; c < 4; ++c) acc2[p][c] = 0ull;
#pragma unroll 4
    for (int k = 0; k < DD; ++k) {
        float4 wv = reinterpret_cast<const float4*>(Ws + k * DD)[lane];
        u64 w0 = dup_f32x2(wv.x), w1 = dup_f32x2(wv.y);
        u64 w2 = dup_f32x2(wv.z), w3 = dup_f32x2(wv.w);
        const float* xb = XsT + k * XT_STRIDE + wrow0;
#pragma unroll
        for (int p = 0; p < 4; ++p) {
            u64 xp = *reinterpret_cast<const u64*>(xb + 2 * p);
            acc2[p][0] = ffma2(xp, w0, acc2[p][0]);
            acc2[p][1] = ffma2(xp, w1, acc2[p][1]);
            acc2[p][2] = ffma2(xp, w2, acc2[p][2]);
            acc2[p][3] = ffma2(xp, w3, acc2[p][3]);
        }
    }
#pragma unroll
    for (int p = 0; p < 4; ++p)
#pragma unroll
        for (int c = 0; c < 4; ++c)
            unpack2(acc2[p][c], accf[2 * p][c], accf[2 * p + 1][c]);
}

static __device__ __forceinline__ void warp_ln_stats(float z0, float z1, float z2, float z3,
                                                     float& mean, float& rstd) {
    float s  = z0 + z1 + z2 + z3;
    float s2 = z0 * z0 + z1 * z1 + z2 * z2 + z3 * z3;
#pragma unroll
    for (int off = 16; off; off >>= 1) {
        s  += __shfl_xor_sync(0xffffffffu, s,  off);
        s2 += __shfl_xor_sync(0xffffffffu, s2, off);
    }
    mean = s * (1.0f / DD);
    float var = s2 * (1.0f / DD) - mean * mean;
    rstd = rsqrtf(var + 1e-5f);
}

extern "C" __global__ void __launch_bounds__(256, 2)
k_node(const float* __restrict__ tgt, const float* __restrict__ W,
       const float* __restrict__ coef, const int* __restrict__ edge_order,
       const float* __restrict__ ln_g, const float* __restrict__ ln_b,
       float* __restrict__ out_tgt) {
    extern __shared__ float smf[];
    float* Ws  = smf;
    float* XsT = smf + DD * DD;
    const int tid = threadIdx.x, lane = tid & 31, warp = tid >> 5;
    const size_t rowBase = (size_t)blockIdx.x * ROWS_PER_BLK;

    load_w_smem(Ws, W, tid);

#pragma unroll
    for (int r = 0; r < ROWS_PER_WARP; ++r) {
        int rl = warp * ROWS_PER_WARP + r;
        size_t row = rowBase + rl;
        int b = (int)(row / NTGT);
        int t = (int)(row - (size_t)b * NTGT);
        float4 acc4 = make_float4(0.f, 0.f, 0.f, 0.f);
#pragma unroll
        for (int k = 0; k < NK; ++k) {
            int e   = __ldg(edge_order + (size_t)t * NK + k);
            float c = __ldg(coef       + (size_t)t * NK + k);
            float4 v = reinterpret_cast<const float4*>(g_dbond + ((size_t)b * NE + e) * DD)[lane];
            acc4.x += c * v.x; acc4.y += c * v.y;
            acc4.z += c * v.z; acc4.w += c * v.w;
        }
        const float inv_k = 1.0f / NK;
        int k0 = lane * 4;
        XsT[(k0 + 0) * XT_STRIDE + rl] = acc4.x * inv_k;
        XsT[(k0 + 1) * XT_STRIDE + rl] = acc4.y * inv_k;
        XsT[(k0 + 2) * XT_STRIDE + rl] = acc4.z * inv_k;
        XsT[(k0 + 3) * XT_STRIDE + rl] = acc4.w * inv_k;
    }
    __syncthreads();

    float accf[ROWS_PER_WARP][4];
    gemm_tile2(Ws, XsT, warp * ROWS_PER_WARP, lane, accf);

    const float4 gv = reinterpret_cast<const float4*>(ln_g)[lane];
    const float4 bv = reinterpret_cast<const float4*>(ln_b)[lane];

#pragma unroll
    for (int r = 0; r < ROWS_PER_WARP; ++r) {
        size_t row = rowBase + warp * ROWS_PER_WARP + r;
        float4 t2 = reinterpret_cast<const float4*>(g_tproj2 + row * DD)[lane];

        float z0 = silu_f(accf[r][0] + t2.x);
        float z1 = silu_f(accf[r][1] + t2.y);
        float z2 = silu_f(accf[r][2] + t2.z);
        float z3 = silu_f(accf[r][3] + t2.w);

        float mean, rstd;
        warp_ln_stats(z0, z1, z2, z3, mean, rstd);

        float4 d;
        d.x = (z0 - mean) * rstd * gv.x + bv.x;
        d.y = (z1 - mean) * rstd * gv.y + bv.y;
        d.z = (z2 - mean) * rstd * gv.z + bv.z;
        d.w = (z3 - mean) * rstd * gv.w + bv.w;

        float4 tin = reinterpret_cast<const float4*>(tgt + row * DD)[lane];
        float4 ov = make_float4(tin.x + d.x, tin.y + d.y, tin.z + d.z, tin.w + d.w);
        reinterpret_cast<float4*>(out_tgt + row * DD)[lane] = ov;
    }
}

// ==================== launch =================================================
extern "C" void kernel_launch(void* const* d_in, const int* in_sizes, int n_in,
                              void* d_out, int out_size) {
    const float* bond   = (const float*)d_in[0];
    const float* src    = (const float*)d_in[1];
    const float* tgt    = (const float*)d_in[2];
    const float* W_s2e  = (const float*)d_in[3];
    const float* W_t2e  = (const float*)d_in[4];
    const float* W_e2e  = (const float*)d_in[5];
    const float* ln1_g  = (const float*)d_in[6];
    const float* ln1_b  = (const float*)d_in[7];
    const float* W_e2t  = (const float*)d_in[8];
    const float* W_t2t  = (const float*)d_in[9];
    const float* ln2_g  = (const float*)d_in[10];
    const float* ln2_b  = (const float*)d_in[11];
    const float* coef   = (const float*)d_in[12];
    const int*   so     = (const int*)d_in[13];
    const int*   to     = (const int*)d_in[14];
    const int*   eo     = (const int*)d_in[15];

    float* out = (float*)d_out;
    float* out_bond = out;
    float* out_src  = out + (size_t)NB * NE * DD;
    float* out_tgt  = out_src + (size_t)NB * NSRC * DD;

    cudaFuncSetAttribute(k_bond_mma, cudaFuncAttributeMaxDynamicSharedMemorySize, BW_TOT);
    cudaFuncSetAttribute(k_proj_mma, cudaFuncAttributeMaxDynamicSharedMemorySize, BW_TOT);
    const size_t smemN = SMEM_FLOATS * sizeof(float);
    cudaFuncSetAttribute(k_node, cudaFuncAttributeMaxDynamicSharedMemorySize, (int)smemN);

    float *sproj, *tproj, *tproj2;
    cudaGetSymbolAddress((void**)&sproj,  g_sproj);
    cudaGetSymbolAddress((void**)&tproj,  g_tproj);
    cudaGetSymbolAddress((void**)&tproj2, g_tproj2);

    cudaMemcpyAsync(out_src, src, (size_t)NB * NSRC * DD * sizeof(float),
                    cudaMemcpyDeviceToDevice);

    const int rowsNode = NB * NTGT;                       // 40000
    const int rowsBond = NB * NE;                         // 640000

    k_prep<<<256, 256>>>(W_s2e, W_t2e, W_t2t, W_e2e);

    k_proj_mma<<<3 * NTILES, 256, BW_TOT>>>(src, tgt, sproj, tproj, tproj2);

    k_bond_mma<<<rowsBond / 128, 256, BW_TOT>>>(bond, so, to, ln1_g, ln1_b, out_bond);

    k_node<<<rowsNode / ROWS_PER_BLK, 256, smemN>>>(tgt, W_e2t, coef, eo,
                                                    ln2_g, ln2_b, out_tgt);
}